// round 12
// baseline (speedup 1.0000x reference)
#include <cuda_runtime.h>
#include <math.h>

#define PI 3.14159265358979323846

#define NBIN 30
#define NM1 19
#define NL1 10
#define NA1 20
#define NM2 11
#define NL2 6
#define NA2 12
#define FIN 1029
#define F1C 20
#define F2C 40
#define BATCH 64
#define NGRID 128
#define NK2 144

#define M1 (BATCH*NM1)   // 1216
#define N1 (F1C*NM1)     // 380
#define K1D FIN          // 1029
#define M2 (BATCH*NM2)   // 704
#define N2 (F2C*NM2)     // 440
#define K2D (F1C*NM2)    // 220

// scratch
__device__ float g_Are[NL1*K1D*M1];
__device__ float g_Aim[NL1*K1D*M1];
__device__ float g_Bre[NL1*K1D*N1];
__device__ float g_Bim[NL1*K1D*N1];
__device__ float g_Cre[NL1*M1*N1];
__device__ float g_Cim[NL1*M1*N1];
__device__ float g_x1[BATCH*F1C*NA1*NA1*NA1];
__device__ float g_A2re[NL2*K2D*M2];
__device__ float g_A2im[NL2*K2D*M2];
__device__ float g_B2re[NL2*K2D*N2];
__device__ float g_B2im[NL2*K2D*N2];
__device__ float g_C2re[NL2*M2*N2];
__device__ float g_C2im[NL2*M2*N2];
__device__ float g_feat[BATCH*F2C];

// basis
__device__ float  g_d0w[NBIN*NL1*NM1];
__device__ float2 g_EaIN[NBIN*NM1];
__device__ float2 g_K1[NGRID*NL1*NM1];
__device__ float  g_d4s1[NA1*NL1*NM1*NM1];
__device__ float2 g_Es1[NM1*NA1];
__device__ float  g_d4a2[NA1*NL2*NM2*NM2];
__device__ float2 g_Ea2[NA1*NM2];
__device__ float2 g_K2[NK2*NL2*NM2*NM2];
__device__ float  g_d4s2[NA2*NL2*NM2*NM2];
__device__ float2 g_Es2[NM2*NA2];
__device__ float  g_wint[NA2];
__device__ double g_bg[NGRID];
__device__ double g_ag[NGRID];

__device__ __forceinline__ int imax(int a,int b){return a>b?a:b;}
__device__ __forceinline__ int imin(int a,int b){return a<b?a:b;}

__device__ __forceinline__ double dfact(int n){
    const double f[19] = {1.,1.,2.,6.,24.,120.,720.,5040.,40320.,362880.,3628800.,
        39916800.,479001600.,6227020800.,87178291200.,1307674368000.,
        20922789888000.,355687428096000.,6402373705728000.};
    return f[n];
}

__device__ double wigd(int l,int mp,int mm,double beta){
    double cb=cos(0.5*beta), sb=sin(0.5*beta);
    double pref=sqrt(dfact(l+mp)*dfact(l-mp)*dfact(l+mm)*dfact(l-mm));
    int s0=imax(0,mm-mp), s1=imin(l+mm,l-mp);
    double v=0.0;
    for(int s=s0;s<=s1;s++){
        double term=(((mp-mm+s)&1)?-1.0:1.0)
            /(dfact(l+mm-s)*dfact(s)*dfact(mp-mm+s)*dfact(l-mp-s));
        int ec=2*l+mm-mp-2*s, es=mp-mm+2*s;
        double cp=1.0; for(int t=0;t<ec;t++) cp*=cb;
        double sp=1.0; for(int t=0;t<es;t++) sp*=sb;
        v+=term*cp*sp;
    }
    return pref*v;
}

__device__ double dhw(int b,int k){
    double beta=PI*(2*k+1)/(4.0*b);
    double s=0.0;
    for(int j=0;j<b;j++) s+=sin(beta*(2*j+1))/(double)(2*j+1);
    return (2.0/b)*sin(beta)*s;
}

// numpy default_rng(42): SeedSequence -> PCG64 (xsl-rr-128/64)
__global__ void k_rng(){
    if(threadIdx.x!=0||blockIdx.x!=0) return;
    unsigned int pool[4];
    unsigned int hc=0x43b0d7e5u;
    auto hashmix=[&hc](unsigned int v){ v^=hc; hc*=0x931e8875u; v*=hc; v^=v>>16; return v; };
    pool[0]=hashmix(42u);
    for(int i=1;i<4;i++) pool[i]=hashmix(0u);
    for(int s=0;s<4;s++)
        for(int d=0;d<4;d++)
            if(s!=d){
                unsigned int h=hashmix(pool[s]);
                unsigned int r=pool[d]*0xca01f9ddu - h*0x4973f715u;
                r^=r>>16;
                pool[d]=r;
            }
    unsigned int hb=0x8b51f9ddu;
    unsigned int st32[8];
    for(int i=0;i<8;i++){
        unsigned int v=pool[i&3];
        v^=hb; hb*=0x58f38dedu; v*=hb; v^=v>>16;
        st32[i]=v;
    }
    unsigned long long w[4];
    for(int i=0;i<4;i++)
        w[i]=(unsigned long long)st32[2*i] | ((unsigned long long)st32[2*i+1]<<32);
    unsigned long long s_hi=w[0], s_lo=w[1];
    unsigned long long q_hi=w[2], q_lo=w[3];
    unsigned long long inc_hi=(q_hi<<1)|(q_lo>>63);
    unsigned long long inc_lo=(q_lo<<1)|1ull;
    const unsigned long long M_hi=0x2360ed051fc65da4ull, M_lo=0x4385df649fccf645ull;
    unsigned long long st_hi=0ull, st_lo=0ull;
    auto step=[&](){
        unsigned long long lo=st_lo*M_lo;
        unsigned long long hi=__umul64hi(st_lo,M_lo)+st_lo*M_hi+st_hi*M_lo;
        lo+=inc_lo;
        hi+=inc_hi+(lo<inc_lo?1ull:0ull);
        st_lo=lo; st_hi=hi;
    };
    step();
    { unsigned long long nl=st_lo+s_lo;
      st_hi+=s_hi+(nl<st_lo?1ull:0ull);
      st_lo=nl; }
    step();
    for(int i=0;i<2*NGRID;i++){
        step();
        unsigned long long xo=st_hi^st_lo;
        unsigned int rot=(unsigned int)(st_hi>>58);
        unsigned long long r64=(xo>>rot)|(xo<<((64u-rot)&63u));
        double u=(double)(r64>>11)*(1.0/9007199254740992.0);
        if(i<NGRID) g_bg[i]=acos(-1.0+2.0*u);
        else        g_ag[i-NGRID]=2.0*PI*u;
    }
}

__global__ void k_bas_d0w(){
    int idx=blockIdx.x*blockDim.x+threadIdx.x;
    if(idx>=NBIN*NL1*NM1) return;
    int k=idx/(NL1*NM1), l=(idx/NM1)%NL1, m=idx%NM1;
    int mv=m-(NL1-1);
    float v=0.f;
    if(mv>=-l&&mv<=l){
        double beta=PI*(2*k+1)/60.0;
        v=(float)(wigd(l,mv,0,beta)*dhw(15,k)/(4.0*PI));
    }
    g_d0w[idx]=v;
}
__global__ void k_bas_EaIN(){
    int idx=blockIdx.x*blockDim.x+threadIdx.x;
    if(idx>=NBIN*NM1) return;
    int a=idx/NM1, m=idx%NM1;
    double th=(2.0*PI*a/NBIN)*(double)(m-(NL1-1));
    double sc=2.0*PI/NBIN;
    g_EaIN[idx]=make_float2((float)(cos(th)*sc),(float)(-sin(th)*sc));
}
__global__ void k_bas_K1(){
    int idx=blockIdx.x*blockDim.x+threadIdx.x;
    if(idx>=NGRID*NL1*NM1) return;
    int j=idx/(NL1*NM1), l=(idx/NM1)%NL1, m=idx%NM1;
    int mv=m-(NL1-1);
    float2 v=make_float2(0.f,0.f);
    if(mv>=-l&&mv<=l){
        double d0=wigd(l,mv,0,g_bg[j]);
        double th=g_ag[j]*(double)mv;
        v=make_float2((float)(d0*cos(th)),(float)(-d0*sin(th)));
    }
    g_K1[idx]=v;
}
__global__ void k_bas_d4s1(){
    int idx=blockIdx.x*blockDim.x+threadIdx.x;
    if(idx>=NA1*NL1*NM1*NM1) return;
    int k=idx/(NL1*NM1*NM1), l=(idx/(NM1*NM1))%NL1;
    int m=(idx/NM1)%NM1, n=idx%NM1;
    int mv=m-(NL1-1), nv=n-(NL1-1);
    float v=0.f;
    if(mv>=-l&&mv<=l&&nv>=-l&&nv<=l){
        double beta=PI*(2*k+1)/40.0;
        v=(float)(wigd(l,mv,nv,beta)*(double)(2*l+1));
    }
    g_d4s1[idx]=v;
}
__global__ void k_bas_Es1(){
    int idx=blockIdx.x*blockDim.x+threadIdx.x;
    if(idx>=NM1*NA1) return;
    int m=idx/NA1, a=idx%NA1;
    double th=(double)(m-(NL1-1))*(2.0*PI*a/NA1);
    g_Es1[idx]=make_float2((float)cos(th),(float)sin(th));
}
__global__ void k_bas_d4a2(){
    int idx=blockIdx.x*blockDim.x+threadIdx.x;
    if(idx>=NA1*NL2*NM2*NM2) return;
    int k=idx/(NL2*NM2*NM2), l=(idx/(NM2*NM2))%NL2;
    int m=(idx/NM2)%NM2, n=idx%NM2;
    int mv=m-(NL2-1), nv=n-(NL2-1);
    float v=0.f;
    if(mv>=-l&&mv<=l&&nv>=-l&&nv<=l){
        double beta=PI*(2*k+1)/40.0;
        v=(float)(wigd(l,mv,nv,beta)*dhw(10,k)/(8.0*PI*PI));
    }
    g_d4a2[idx]=v;
}
__global__ void k_bas_Ea2(){
    int idx=blockIdx.x*blockDim.x+threadIdx.x;
    if(idx>=NA1*NM2) return;
    int a=idx/NM2, m=idx%NM2;
    double th=(2.0*PI*a/NA1)*(double)(m-(NL2-1));
    double sc=2.0*PI/NA1;
    g_Ea2[idx]=make_float2((float)(cos(th)*sc),(float)(-sin(th)*sc));
}
__global__ void k_bas_K2(){
    int idx=blockIdx.x*blockDim.x+threadIdx.x;
    if(idx>=NK2*NL2*NM2*NM2) return;
    int j=idx/(NL2*NM2*NM2), l=(idx/(NM2*NM2))%NL2;
    int m=(idx/NM2)%NM2, n=idx%NM2;
    int mv=m-(NL2-1), nv=n-(NL2-1);
    float2 v=make_float2(0.f,0.f);
    if(mv>=-l&&mv<=l&&nv>=-l&&nv<=l){
        int ib=j/48, ia=(j/6)%8, ig=j%6;
        double beta=(double)(ib+1)*(PI/8.0)/3.0;
        double alpha=2.0*PI*ia/8.0;
        double gamma=2.0*PI*ig/6.0;
        double d=wigd(l,mv,nv,beta);
        double th=alpha*(double)mv+gamma*(double)nv;
        v=make_float2((float)(d*cos(th)),(float)(-d*sin(th)));
    }
    g_K2[idx]=v;
}
__global__ void k_bas_d4s2(){
    int idx=blockIdx.x*blockDim.x+threadIdx.x;
    if(idx>=NA2*NL2*NM2*NM2) return;
    int k=idx/(NL2*NM2*NM2), l=(idx/(NM2*NM2))%NL2;
    int m=(idx/NM2)%NM2, n=idx%NM2;
    int mv=m-(NL2-1), nv=n-(NL2-1);
    float v=0.f;
    if(mv>=-l&&mv<=l&&nv>=-l&&nv<=l){
        double beta=PI*(2*k+1)/24.0;
        v=(float)(wigd(l,mv,nv,beta)*(double)(2*l+1));
    }
    g_d4s2[idx]=v;
}
__global__ void k_bas_Es2Wint(){
    int idx=blockIdx.x*blockDim.x+threadIdx.x;
    if(idx<NM2*NA2){
        int m=idx/NA2, a=idx%NA2;
        double th=(double)(m-(NL2-1))*(2.0*PI*a/NA2);
        g_Es2[idx]=make_float2((float)cos(th),(float)sin(th));
    } else if(idx<NM2*NA2+NA2){
        int k=idx-NM2*NA2;
        double sc=(2.0*PI/NA2)*(2.0*PI/NA2)/(8.0*PI*PI);
        g_wint[k]=(float)(dhw(6,k)*sc);
    }
}

// S2 analysis: xh[b,f,l,m] -> A[l][f][b*19+m]
__global__ void k_xh(const float* __restrict__ x){
    int f=blockIdx.x, b=blockIdx.y;
    int tid=threadIdx.x; // 192
    __shared__ float  sx[NBIN*NBIN];
    __shared__ float2 sEa[NBIN*NM1];
    __shared__ float2 se[NBIN*NM1];
    size_t xbase=((size_t)b*FIN+f)*(NBIN*NBIN);
    for(int i=tid;i<NBIN*NBIN;i+=blockDim.x) sx[i]=x[xbase+i];
    for(int i=tid;i<NBIN*NM1;i+=blockDim.x) sEa[i]=g_EaIN[i];
    __syncthreads();
    for(int i=tid;i<NBIN*NM1;i+=blockDim.x){
        int k=i/NM1, m=i%NM1;
        float re=0.f, im=0.f;
        #pragma unroll 6
        for(int a=0;a<NBIN;a++){
            float xv=sx[k*NBIN+a];
            float2 e=sEa[a*NM1+m];
            re=fmaf(xv,e.x,re);
            im=fmaf(xv,e.y,im);
        }
        se[i]=make_float2(re,im);
    }
    __syncthreads();
    for(int i=tid;i<NL1*NM1;i+=blockDim.x){
        int l=i/NM1, m=i%NM1;
        float re=0.f, im=0.f;
        #pragma unroll 6
        for(int k=0;k<NBIN;k++){
            float w=g_d0w[(k*NL1+l)*NM1+m];
            float2 e=se[k*NM1+m];
            re=fmaf(w,e.x,re);
            im=fmaf(w,e.y,im);
        }
        size_t off=((size_t)l*FIN+f)*M1+b*NM1+m;
        g_Are[off]=re;
        g_Aim[off]=im;
    }
}

// conj(yh)[f,g,l,n] -> B[l][f][g*19+n]
__global__ void k_yh1(const float* __restrict__ kern1){
    int f=blockIdx.x, l=blockIdx.y;
    int tid=threadIdx.x; // 256
    __shared__ float  sk1[F1C*NGRID];
    __shared__ float2 sK1[NGRID*NM1];
    size_t kb=(size_t)f*F1C*NGRID;
    for(int i=tid;i<F1C*NGRID;i+=blockDim.x) sk1[i]=kern1[kb+i];
    for(int i=tid;i<NGRID*NM1;i+=blockDim.x){
        int j=i/NM1, n=i%NM1;
        float2 v=g_K1[(j*NL1+l)*NM1+n];
        sK1[i]=make_float2(v.x,-v.y);
    }
    __syncthreads();
    for(int o=tid;o<N1;o+=blockDim.x){
        int g=o/NM1, n=o%NM1;
        float re=0.f, im=0.f;
        #pragma unroll 8
        for(int j=0;j<NGRID;j++){
            float w=sk1[g*NGRID+j];
            float2 kv=sK1[j*NM1+n];
            re=fmaf(w,kv.x,re);
            im=fmaf(w,kv.y,im);
        }
        size_t off=((size_t)l*FIN+f)*N1+o;
        g_Bre[off]=re;
        g_Bim[off]=im;
    }
}

// complex TN GEMM: C[l][m][n] = sum_k A[l][k][m]*B[l][k][n]
__global__ void k_cgemm(int layer,int M,int N,int K){
    const float *Are,*Aim,*Bre,*Bim; float *Cre,*Cim;
    if(layer==0){Are=g_Are;Aim=g_Aim;Bre=g_Bre;Bim=g_Bim;Cre=g_Cre;Cim=g_Cim;}
    else        {Are=g_A2re;Aim=g_A2im;Bre=g_B2re;Bim=g_B2im;Cre=g_C2re;Cim=g_C2im;}
    int l=blockIdx.z;
    const float* are=Are+(size_t)l*K*M;
    const float* aim=Aim+(size_t)l*K*M;
    const float* bre=Bre+(size_t)l*K*N;
    const float* bim=Bim+(size_t)l*K*N;
    float* cre=Cre+(size_t)l*M*N;
    float* cim=Cim+(size_t)l*M*N;
    int m0=blockIdx.x*64, n0=blockIdx.y*64;
    __shared__ __align__(16) float sAr[8][64],sAi[8][64],sBr[8][64],sBi[8][64];
    int tid=threadIdx.x; // 256
    int tx=tid&15, ty=tid>>4;
    float cr[4][4]={}, ci[4][4]={};
    for(int k0=0;k0<K;k0+=8){
        #pragma unroll
        for(int it=0;it<2;it++){
            int idx=tid+it*256;
            int kk=idx>>6, col=idx&63;
            int krow=k0+kk;
            float ar=0.f,ai=0.f,br=0.f,bi=0.f;
            if(krow<K){
                int mc=m0+col;
                if(mc<M){ ar=are[(size_t)krow*M+mc]; ai=aim[(size_t)krow*M+mc]; }
                int nc=n0+col;
                if(nc<N){ br=bre[(size_t)krow*N+nc]; bi=bim[(size_t)krow*N+nc]; }
            }
            sAr[kk][col]=ar; sAi[kk][col]=ai;
            sBr[kk][col]=br; sBi[kk][col]=bi;
        }
        __syncthreads();
        #pragma unroll
        for(int kk=0;kk<8;kk++){
            float4 arv=*reinterpret_cast<const float4*>(&sAr[kk][ty*4]);
            float4 aiv=*reinterpret_cast<const float4*>(&sAi[kk][ty*4]);
            float4 brv=*reinterpret_cast<const float4*>(&sBr[kk][tx*4]);
            float4 biv=*reinterpret_cast<const float4*>(&sBi[kk][tx*4]);
            float ar[4]={arv.x,arv.y,arv.z,arv.w};
            float ai[4]={aiv.x,aiv.y,aiv.z,aiv.w};
            float br[4]={brv.x,brv.y,brv.z,brv.w};
            float bi[4]={biv.x,biv.y,biv.z,biv.w};
            #pragma unroll
            for(int i=0;i<4;i++)
                #pragma unroll
                for(int j=0;j<4;j++){
                    cr[i][j]=fmaf(ar[i],br[j],cr[i][j]);
                    cr[i][j]=fmaf(-ai[i],bi[j],cr[i][j]);
                    ci[i][j]=fmaf(ar[i],bi[j],ci[i][j]);
                    ci[i][j]=fmaf(ai[i],br[j],ci[i][j]);
                }
        }
        __syncthreads();
    }
    #pragma unroll
    for(int i=0;i<4;i++){
        int m=m0+ty*4+i;
        if(m>=M) continue;
        #pragma unroll
        for(int j=0;j<4;j++){
            int n=n0+tx*4+j;
            if(n<N){
                cre[(size_t)m*N+n]=cr[i][j];
                cim[(size_t)m*N+n]=ci[i][j];
            }
        }
    }
}

// SO3 synthesis b1 + bias + relu -> x1[b,g,k,a,c]
__global__ void k_syn1(const float* __restrict__ bias1){
    int g=blockIdx.x, b=blockIdx.y;
    int tid=threadIdx.x; // 256
    __shared__ float2 sz[NL1*NM1*NM1];
    __shared__ float2 ssk[NM1*NM1];
    __shared__ float2 st[NA1*NM1];
    for(int i=tid;i<NL1*NM1*NM1;i+=blockDim.x){
        int l=i/(NM1*NM1), r=i%(NM1*NM1);
        int m=r/NM1, n=r%NM1;
        size_t off=((size_t)l*M1+b*NM1+m)*N1+g*NM1+n;
        sz[i]=make_float2(g_Cre[off],g_Cim[off]);
    }
    __syncthreads();
    float bv=bias1[g];
    for(int k=0;k<NA1;k++){
        for(int i=tid;i<NM1*NM1;i+=blockDim.x){
            float re=0.f, im=0.f;
            #pragma unroll
            for(int l=0;l<NL1;l++){
                float w=g_d4s1[(k*NL1+l)*(NM1*NM1)+i];
                float2 z=sz[l*(NM1*NM1)+i];
                re=fmaf(w,z.x,re);
                im=fmaf(w,z.y,im);
            }
            ssk[i]=make_float2(re,im);
        }
        __syncthreads();
        for(int i=tid;i<NA1*NM1;i+=blockDim.x){
            int a=i/NM1, n=i%NM1;
            float re=0.f, im=0.f;
            #pragma unroll
            for(int m=0;m<NM1;m++){
                float2 e=g_Es1[m*NA1+a];
                float2 s=ssk[m*NM1+n];
                re+=s.x*e.x-s.y*e.y;
                im+=s.x*e.y+s.y*e.x;
            }
            st[i]=make_float2(re,im);
        }
        __syncthreads();
        for(int i=tid;i<NA1*NA1;i+=blockDim.x){
            int a=i/NA1, c=i%NA1;
            float v=0.f;
            #pragma unroll
            for(int n=0;n<NM1;n++){
                float2 e=g_Es1[n*NA1+c];
                float2 t=st[a*NM1+n];
                v+=t.x*e.x-t.y*e.y;
            }
            v+=bv;
            v=v>0.f?v:0.f;
            g_x1[(((size_t)(b*F1C+g)*NA1+k)*NA1+a)*NA1+c]=v;
        }
        __syncthreads();
    }
}

// SO3 analysis b1 -> A2[l][f*11+p][b*11+m]
__global__ void k_t2(){
    int f=blockIdx.x, b=blockIdx.y;
    int tid=threadIdx.x; // 128
    __shared__ float  sx1[NA1*NA1];
    __shared__ float2 stt[NA1*NM2];
    __shared__ float2 su[NM2*NM2];
    __shared__ float2 sacc[NL2*NM2*NM2];
    for(int i=tid;i<NL2*NM2*NM2;i+=blockDim.x) sacc[i]=make_float2(0.f,0.f);
    __syncthreads();
    for(int k=0;k<NA1;k++){
        size_t xb=(((size_t)(b*F1C+f)*NA1+k))*NA1*NA1;
        for(int i=tid;i<NA1*NA1;i+=blockDim.x) sx1[i]=g_x1[xb+i];
        __syncthreads();
        for(int i=tid;i<NA1*NM2;i+=blockDim.x){
            int a=i/NM2, n=i%NM2;
            float re=0.f, im=0.f;
            #pragma unroll
            for(int c=0;c<NA1;c++){
                float xv=sx1[a*NA1+c];
                float2 e=g_Ea2[c*NM2+n];
                re=fmaf(xv,e.x,re);
                im=fmaf(xv,e.y,im);
            }
            stt[i]=make_float2(re,im);
        }
        __syncthreads();
        for(int i=tid;i<NM2*NM2;i+=blockDim.x){
            int m=i/NM2, n=i%NM2;
            float re=0.f, im=0.f;
            #pragma unroll
            for(int a=0;a<NA1;a++){
                float2 e=g_Ea2[a*NM2+m];
                float2 t=stt[a*NM2+n];
                re+=t.x*e.x-t.y*e.y;
                im+=t.x*e.y+t.y*e.x;
            }
            su[i]=make_float2(re,im);
        }
        __syncthreads();
        for(int i=tid;i<NL2*NM2*NM2;i+=blockDim.x){
            int l=i/(NM2*NM2), r=i%(NM2*NM2);
            float w=g_d4a2[(k*NL2+l)*(NM2*NM2)+r];
            float2 u=su[r];
            sacc[i].x=fmaf(w,u.x,sacc[i].x);
            sacc[i].y=fmaf(w,u.y,sacc[i].y);
        }
        __syncthreads();
    }
    for(int i=tid;i<NL2*NM2*NM2;i+=blockDim.x){
        int l=i/(NM2*NM2), m=(i/NM2)%NM2, p=i%NM2;
        size_t off=((size_t)l*K2D+f*NM2+p)*M2+b*NM2+m;
        g_A2re[off]=sacc[i].x;
        g_A2im[off]=sacc[i].y;
    }
}

// conj(yh2)[f,g,l,n,p] -> B2[l][f*11+p][g*11+n]
__global__ void k_yh2(const float* __restrict__ kern2){
    int g=blockIdx.x, f=blockIdx.y;
    int tid=threadIdx.x; // 128
    __shared__ float skn[NK2];
    size_t kb=((size_t)f*F2C+g)*NK2;
    for(int i=tid;i<NK2;i+=blockDim.x) skn[i]=kern2[kb+i];
    __syncthreads();
    for(int i=tid;i<NL2*NM2*NM2;i+=blockDim.x){
        int l=i/(NM2*NM2), n=(i/NM2)%NM2, p=i%NM2;
        float re=0.f, im=0.f;
        #pragma unroll 8
        for(int j=0;j<NK2;j++){
            float w=skn[j];
            float2 kv=g_K2[(j*NL2+l)*(NM2*NM2)+n*NM2+p];
            re=fmaf(w,kv.x,re);
            im=fmaf(w,kv.y,im);
        }
        size_t off=((size_t)l*K2D+f*NM2+p)*N2+g*NM2+n;
        g_B2re[off]=re;
        g_B2im[off]=-im;
    }
}

// SO3 synthesis b2 + bias + relu + quadrature -> feat[b,g]
__global__ void k_syn2(const float* __restrict__ bias2){
    int g=blockIdx.x, b=blockIdx.y;
    int tid=threadIdx.x; // 128
    __shared__ float2 sz[NL2*NM2*NM2];
    __shared__ float2 ss[NM2*NM2];
    __shared__ float2 st2[NA2*NM2];
    __shared__ float  sred[128];
    for(int i=tid;i<NL2*NM2*NM2;i+=blockDim.x){
        int l=i/(NM2*NM2), r=i%(NM2*NM2);
        int m=r/NM2, n=r%NM2;
        size_t off=(size_t)l*M2*N2+((size_t)b*NM2+m)*N2+g*NM2+n;
        sz[i]=make_float2(g_C2re[off],g_C2im[off]);
    }
    __syncthreads();
    float bv=bias2[g];
    float acc=0.f;
    for(int k=0;k<NA2;k++){
        for(int i=tid;i<NM2*NM2;i+=blockDim.x){
            float re=0.f, im=0.f;
            #pragma unroll
            for(int l=0;l<NL2;l++){
                float w=g_d4s2[(k*NL2+l)*(NM2*NM2)+i];
                float2 z=sz[l*(NM2*NM2)+i];
                re=fmaf(w,z.x,re);
                im=fmaf(w,z.y,im);
            }
            ss[i]=make_float2(re,im);
        }
        __syncthreads();
        for(int i=tid;i<NA2*NM2;i+=blockDim.x){
            int a=i/NM2, n=i%NM2;
            float re=0.f, im=0.f;
            #pragma unroll
            for(int m=0;m<NM2;m++){
                float2 e=g_Es2[m*NA2+a];
                float2 s=ss[m*NM2+n];
                re+=s.x*e.x-s.y*e.y;
                im+=s.x*e.y+s.y*e.x;
            }
            st2[i]=make_float2(re,im);
        }
        __syncthreads();
        float wk=g_wint[k];
        for(int i=tid;i<NA2*NA2;i+=blockDim.x){
            int a=i/NA2, c=i%NA2;
            float v=0.f;
            #pragma unroll
            for(int n=0;n<NM2;n++){
                float2 e=g_Es2[n*NA2+c];
                float2 t=st2[a*NM2+n];
                v+=t.x*e.x-t.y*e.y;
            }
            v+=bv;
            v=v>0.f?v:0.f;
            acc+=wk*v;
        }
        __syncthreads();
    }
    sred[tid]=acc;
    __syncthreads();
    for(int s=64;s>0;s>>=1){
        if(tid<s) sred[tid]+=sred[tid+s];
        __syncthreads();
    }
    if(tid==0) g_feat[b*F2C+g]=sred[0];
}

__global__ void k_head(const float* __restrict__ W, const float* __restrict__ b_lin,
                       float* __restrict__ out){
    int idx=threadIdx.x;
    if(idx>=BATCH*2) return;
    int b=idx>>1, i=idx&1;
    float s=b_lin[i];
    #pragma unroll 8
    for(int g=0;g<F2C;g++) s+=g_feat[b*F2C+g]*W[i*F2C+g];
    out[idx]=s;
}

extern "C" void kernel_launch(void* const* d_in, const int* in_sizes, int n_in,
                              void* d_out, int out_size){
    const float* x     = (const float*)d_in[0];
    const float* kern1 = (const float*)d_in[1];
    const float* bias1 = (const float*)d_in[2];
    const float* kern2 = (const float*)d_in[3];
    const float* bias2 = (const float*)d_in[4];
    const float* W     = (const float*)d_in[5];
    const float* b_lin = (const float*)d_in[6];
    float* out = (float*)d_out;
    const int T=128;
    k_rng<<<1,32>>>();
    k_bas_d0w<<<(NBIN*NL1*NM1+T-1)/T,T>>>();
    k_bas_EaIN<<<(NBIN*NM1+T-1)/T,T>>>();
    k_bas_K1<<<(NGRID*NL1*NM1+T-1)/T,T>>>();
    k_bas_d4s1<<<(NA1*NL1*NM1*NM1+T-1)/T,T>>>();
    k_bas_Es1<<<(NM1*NA1+T-1)/T,T>>>();
    k_bas_d4a2<<<(NA1*NL2*NM2*NM2+T-1)/T,T>>>();
    k_bas_Ea2<<<(NA1*NM2+T-1)/T,T>>>();
    k_bas_K2<<<(NK2*NL2*NM2*NM2+T-1)/T,T>>>();
    k_bas_d4s2<<<(NA2*NL2*NM2*NM2+T-1)/T,T>>>();
    k_bas_Es2Wint<<<(NM2*NA2+NA2+T-1)/T,T>>>();
    k_xh<<<dim3(FIN,BATCH),192>>>(x);
    k_yh1<<<dim3(FIN,NL1),256>>>(kern1);
    k_cgemm<<<dim3((M1+63)/64,(N1+63)/64,NL1),256>>>(0,M1,N1,K1D);
    k_syn1<<<dim3(F1C,BATCH),256>>>(bias1);
    k_t2<<<dim3(F1C,BATCH),128>>>();
    k_yh2<<<dim3(F2C,F1C),128>>>(kern2);
    k_cgemm<<<dim3((M2+63)/64,(N2+63)/64,NL2),256>>>(1,M2,N2,K2D);
    k_syn2<<<dim3(F2C,BATCH),128>>>(bias2);
    k_head<<<1,128>>>(W,b_lin,out);
}

// round 13
// speedup vs baseline: 1.3792x; 1.3792x over previous
#include <cuda_runtime.h>
#include <math.h>

#define PI 3.14159265358979323846

#define NBIN 30
#define NM1 19
#define NL1 10
#define NA1 20
#define NM2 11
#define NL2 6
#define NA2 12
#define FIN 1029
#define F1C 20
#define F2C 40
#define BATCH 64
#define NGRID 128
#define NK2 144

#define M1 (BATCH*NM1)   // 1216 (row stride)
#define N1 (F1C*NM1)     // 380
#define K1D FIN          // 1029
#define M2 (BATCH*NM2)   // 704
#define N2 (F2C*NM2)     // 440
#define K2D (F1C*NM2)    // 220

// scratch
__device__ float g_Are[NL1*K1D*M1];
__device__ float g_Aim[NL1*K1D*M1];
__device__ float g_Bre[NL1*K1D*N1];
__device__ float g_Bim[NL1*K1D*N1];
__device__ float g_Cre[NL1*M1*N1];
__device__ float g_Cim[NL1*M1*N1];
__device__ float g_x1[BATCH*F1C*NA1*NA1*NA1];
__device__ float g_A2re[NL2*K2D*M2];
__device__ float g_A2im[NL2*K2D*M2];
__device__ float g_B2re[NL2*K2D*N2];
__device__ float g_B2im[NL2*K2D*N2];
__device__ float g_C2re[NL2*M2*N2];
__device__ float g_C2im[NL2*M2*N2];
__device__ float g_feat[BATCH*F2C];

// basis
__device__ float  g_d0w[NBIN*NL1*NM1];
__device__ float2 g_EaIN[NBIN*NM1];
__device__ float2 g_K1[NGRID*NL1*NM1];
__device__ float  g_d4s1[NA1*NL1*NM1*NM1];
__device__ float2 g_Es1[NM1*NA1];
__device__ float  g_d4a2[NA1*NL2*NM2*NM2];
__device__ float2 g_Ea2[NA1*NM2];
__device__ float2 g_K2[NK2*NL2*NM2*NM2];
__device__ float  g_d4s2[NA2*NL2*NM2*NM2];
__device__ float2 g_Es2[NM2*NA2];
__device__ float  g_wint[NA2];
__device__ double g_bg[NGRID];
__device__ double g_ag[NGRID];

// per-l flattened offsets: sum_{j<l}(2j+1)^2
__device__ __constant__ int c_S10[11] = {0,1,10,35,84,165,286,455,680,969,1330};
__device__ __constant__ int c_S6[7]   = {0,1,10,35,84,165,286};

__device__ __forceinline__ int imax(int a,int b){return a>b?a:b;}
__device__ __forceinline__ int imin(int a,int b){return a<b?a:b;}

__device__ __forceinline__ double dfact(int n){
    const double f[19] = {1.,1.,2.,6.,24.,120.,720.,5040.,40320.,362880.,3628800.,
        39916800.,479001600.,6227020800.,87178291200.,1307674368000.,
        20922789888000.,355687428096000.,6402373705728000.};
    return f[n];
}

__device__ double wigd(int l,int mp,int mm,double beta){
    double cb=cos(0.5*beta), sb=sin(0.5*beta);
    double pref=sqrt(dfact(l+mp)*dfact(l-mp)*dfact(l+mm)*dfact(l-mm));
    int s0=imax(0,mm-mp), s1=imin(l+mm,l-mp);
    double v=0.0;
    for(int s=s0;s<=s1;s++){
        double term=(((mp-mm+s)&1)?-1.0:1.0)
            /(dfact(l+mm-s)*dfact(s)*dfact(mp-mm+s)*dfact(l-mp-s));
        int ec=2*l+mm-mp-2*s, es=mp-mm+2*s;
        double cp=1.0; for(int t=0;t<ec;t++) cp*=cb;
        double sp=1.0; for(int t=0;t<es;t++) sp*=sb;
        v+=term*cp*sp;
    }
    return pref*v;
}

__device__ double dhw(int b,int k){
    double beta=PI*(2*k+1)/(4.0*b);
    double s=0.0;
    for(int j=0;j<b;j++) s+=sin(beta*(2*j+1))/(double)(2*j+1);
    return (2.0/b)*sin(beta)*s;
}

// numpy default_rng(42): SeedSequence -> PCG64 (xsl-rr-128/64)
__global__ void k_rng(){
    if(threadIdx.x!=0||blockIdx.x!=0) return;
    unsigned int pool[4];
    unsigned int hc=0x43b0d7e5u;
    auto hashmix=[&hc](unsigned int v){ v^=hc; hc*=0x931e8875u; v*=hc; v^=v>>16; return v; };
    pool[0]=hashmix(42u);
    for(int i=1;i<4;i++) pool[i]=hashmix(0u);
    for(int s=0;s<4;s++)
        for(int d=0;d<4;d++)
            if(s!=d){
                unsigned int h=hashmix(pool[s]);
                unsigned int r=pool[d]*0xca01f9ddu - h*0x4973f715u;
                r^=r>>16;
                pool[d]=r;
            }
    unsigned int hb=0x8b51f9ddu;
    unsigned int st32[8];
    for(int i=0;i<8;i++){
        unsigned int v=pool[i&3];
        v^=hb; hb*=0x58f38dedu; v*=hb; v^=v>>16;
        st32[i]=v;
    }
    unsigned long long w[4];
    for(int i=0;i<4;i++)
        w[i]=(unsigned long long)st32[2*i] | ((unsigned long long)st32[2*i+1]<<32);
    unsigned long long s_hi=w[0], s_lo=w[1];
    unsigned long long q_hi=w[2], q_lo=w[3];
    unsigned long long inc_hi=(q_hi<<1)|(q_lo>>63);
    unsigned long long inc_lo=(q_lo<<1)|1ull;
    const unsigned long long M_hi=0x2360ed051fc65da4ull, M_lo=0x4385df649fccf645ull;
    unsigned long long st_hi=0ull, st_lo=0ull;
    auto step=[&](){
        unsigned long long lo=st_lo*M_lo;
        unsigned long long hi=__umul64hi(st_lo,M_lo)+st_lo*M_hi+st_hi*M_lo;
        lo+=inc_lo;
        hi+=inc_hi+(lo<inc_lo?1ull:0ull);
        st_lo=lo; st_hi=hi;
    };
    step();
    { unsigned long long nl=st_lo+s_lo;
      st_hi+=s_hi+(nl<st_lo?1ull:0ull);
      st_lo=nl; }
    step();
    for(int i=0;i<2*NGRID;i++){
        step();
        unsigned long long xo=st_hi^st_lo;
        unsigned int rot=(unsigned int)(st_hi>>58);
        unsigned long long r64=(xo>>rot)|(xo<<((64u-rot)&63u));
        double u=(double)(r64>>11)*(1.0/9007199254740992.0);
        if(i<NGRID) g_bg[i]=acos(-1.0+2.0*u);
        else        g_ag[i-NGRID]=2.0*PI*u;
    }
}

// d0w + EaIN merged
__global__ void k_bas1(){
    int idx=blockIdx.x*blockDim.x+threadIdx.x;
    if(idx<NBIN*NL1*NM1){
        int k=idx/(NL1*NM1), l=(idx/NM1)%NL1, m=idx%NM1;
        int mv=m-(NL1-1);
        float v=0.f;
        if(mv>=-l&&mv<=l){
            double beta=PI*(2*k+1)/60.0;
            v=(float)(wigd(l,mv,0,beta)*dhw(15,k)/(4.0*PI));
        }
        g_d0w[idx]=v;
        return;
    }
    idx-=NBIN*NL1*NM1;
    if(idx<NBIN*NM1){
        int a=idx/NM1, m=idx%NM1;
        double th=(2.0*PI*a/NBIN)*(double)(m-(NL1-1));
        double sc=2.0*PI/NBIN;
        g_EaIN[idx]=make_float2((float)(cos(th)*sc),(float)(-sin(th)*sc));
    }
}
__global__ void k_bas_K1(){
    int idx=blockIdx.x*blockDim.x+threadIdx.x;
    if(idx>=NGRID*NL1*NM1) return;
    int j=idx/(NL1*NM1), l=(idx/NM1)%NL1, m=idx%NM1;
    int mv=m-(NL1-1);
    float2 v=make_float2(0.f,0.f);
    if(mv>=-l&&mv<=l){
        double d0=wigd(l,mv,0,g_bg[j]);
        double th=g_ag[j]*(double)mv;
        v=make_float2((float)(d0*cos(th)),(float)(-d0*sin(th)));
    }
    g_K1[idx]=v;
}
// d4s1 + Es1 merged
__global__ void k_basA(){
    int idx=blockIdx.x*blockDim.x+threadIdx.x;
    if(idx<NA1*NL1*NM1*NM1){
        int k=idx/(NL1*NM1*NM1), l=(idx/(NM1*NM1))%NL1;
        int m=(idx/NM1)%NM1, n=idx%NM1;
        int mv=m-(NL1-1), nv=n-(NL1-1);
        float v=0.f;
        if(mv>=-l&&mv<=l&&nv>=-l&&nv<=l){
            double beta=PI*(2*k+1)/40.0;
            v=(float)(wigd(l,mv,nv,beta)*(double)(2*l+1));
        }
        g_d4s1[idx]=v;
        return;
    }
    idx-=NA1*NL1*NM1*NM1;
    if(idx<NM1*NA1){
        int m=idx/NA1, a=idx%NA1;
        double th=(double)(m-(NL1-1))*(2.0*PI*a/NA1);
        g_Es1[idx]=make_float2((float)cos(th),(float)sin(th));
    }
}
// d4a2 + Ea2 + K2 + d4s2 + Es2 + wint merged
__global__ void k_basB(){
    int idx=blockIdx.x*blockDim.x+threadIdx.x;
    if(idx<NA1*NL2*NM2*NM2){
        int k=idx/(NL2*NM2*NM2), l=(idx/(NM2*NM2))%NL2;
        int m=(idx/NM2)%NM2, n=idx%NM2;
        int mv=m-(NL2-1), nv=n-(NL2-1);
        float v=0.f;
        if(mv>=-l&&mv<=l&&nv>=-l&&nv<=l){
            double beta=PI*(2*k+1)/40.0;
            v=(float)(wigd(l,mv,nv,beta)*dhw(10,k)/(8.0*PI*PI));
        }
        g_d4a2[idx]=v;
        return;
    }
    idx-=NA1*NL2*NM2*NM2;
    if(idx<NA1*NM2){
        int a=idx/NM2, m=idx%NM2;
        double th=(2.0*PI*a/NA1)*(double)(m-(NL2-1));
        double sc=2.0*PI/NA1;
        g_Ea2[idx]=make_float2((float)(cos(th)*sc),(float)(-sin(th)*sc));
        return;
    }
    idx-=NA1*NM2;
    if(idx<NK2*NL2*NM2*NM2){
        int j=idx/(NL2*NM2*NM2), l=(idx/(NM2*NM2))%NL2;
        int m=(idx/NM2)%NM2, n=idx%NM2;
        int mv=m-(NL2-1), nv=n-(NL2-1);
        float2 v=make_float2(0.f,0.f);
        if(mv>=-l&&mv<=l&&nv>=-l&&nv<=l){
            int ib=j/48, ia=(j/6)%8, ig=j%6;
            double beta=(double)(ib+1)*(PI/8.0)/3.0;
            double alpha=2.0*PI*ia/8.0;
            double gamma=2.0*PI*ig/6.0;
            double d=wigd(l,mv,nv,beta);
            double th=alpha*(double)mv+gamma*(double)nv;
            v=make_float2((float)(d*cos(th)),(float)(-d*sin(th)));
        }
        g_K2[idx]=v;
        return;
    }
    idx-=NK2*NL2*NM2*NM2;
    if(idx<NA2*NL2*NM2*NM2){
        int k=idx/(NL2*NM2*NM2), l=(idx/(NM2*NM2))%NL2;
        int m=(idx/NM2)%NM2, n=idx%NM2;
        int mv=m-(NL2-1), nv=n-(NL2-1);
        float v=0.f;
        if(mv>=-l&&mv<=l&&nv>=-l&&nv<=l){
            double beta=PI*(2*k+1)/24.0;
            v=(float)(wigd(l,mv,nv,beta)*(double)(2*l+1));
        }
        g_d4s2[idx]=v;
        return;
    }
    idx-=NA2*NL2*NM2*NM2;
    if(idx<NM2*NA2){
        int m=idx/NA2, a=idx%NA2;
        double th=(double)(m-(NL2-1))*(2.0*PI*a/NA2);
        g_Es2[idx]=make_float2((float)cos(th),(float)sin(th));
        return;
    }
    idx-=NM2*NA2;
    if(idx<NA2){
        double sc=(2.0*PI/NA2)*(2.0*PI/NA2)/(8.0*PI*PI);
        g_wint[idx]=(float)(dhw(6,idx)*sc);
    }
}

// S2 analysis: packed A[l][f][ b*(2l+1)+mi ], mi = m+l
__global__ void k_xh(const float* __restrict__ x){
    int f=blockIdx.x, b=blockIdx.y;
    int tid=threadIdx.x; // 192
    __shared__ float  sx[NBIN*NBIN];
    __shared__ float2 sEa[NBIN*NM1];
    __shared__ float2 se[NBIN*NM1];
    size_t xbase=((size_t)b*FIN+f)*(NBIN*NBIN);
    for(int i=tid;i<NBIN*NBIN;i+=blockDim.x) sx[i]=x[xbase+i];
    for(int i=tid;i<NBIN*NM1;i+=blockDim.x) sEa[i]=g_EaIN[i];
    __syncthreads();
    for(int i=tid;i<NBIN*NM1;i+=blockDim.x){
        int k=i/NM1, m=i%NM1;
        float re=0.f, im=0.f;
        #pragma unroll 6
        for(int a=0;a<NBIN;a++){
            float xv=sx[k*NBIN+a];
            float2 e=sEa[a*NM1+m];
            re=fmaf(xv,e.x,re);
            im=fmaf(xv,e.y,im);
        }
        se[i]=make_float2(re,im);
    }
    __syncthreads();
    // 100 valid (l, mi) pairs; offsets are l^2
    for(int i=tid;i<NL1*NL1;i+=blockDim.x){
        int l=(int)sqrtf((float)i+0.5f);
        while(l*l>i) l--;
        while((l+1)*(l+1)<=i) l++;
        int mi=i-l*l;            // 0..2l
        int m=mi-l+(NL1-1);      // global m index
        float re=0.f, im=0.f;
        #pragma unroll 6
        for(int k=0;k<NBIN;k++){
            float w=g_d0w[(k*NL1+l)*NM1+m];
            float2 e=se[k*NM1+m];
            re=fmaf(w,e.x,re);
            im=fmaf(w,e.y,im);
        }
        size_t off=((size_t)l*FIN+f)*M1 + b*(2*l+1)+mi;
        g_Are[off]=re;
        g_Aim[off]=im;
    }
}

// conj(yh)[f,g,l,ni] packed -> B[l][f][ g*(2l+1)+ni ]
__global__ void k_yh1(const float* __restrict__ kern1){
    int f=blockIdx.x, l=blockIdx.y;
    int w=2*l+1;
    int tid=threadIdx.x; // 256
    __shared__ float  sk1[F1C*NGRID];
    __shared__ float2 sK1[NGRID*NM1];
    size_t kb=(size_t)f*F1C*NGRID;
    for(int i=tid;i<F1C*NGRID;i+=blockDim.x) sk1[i]=kern1[kb+i];
    for(int i=tid;i<NGRID*NM1;i+=blockDim.x){
        int j=i/NM1, n=i%NM1;
        float2 v=g_K1[(j*NL1+l)*NM1+n];
        sK1[i]=make_float2(v.x,-v.y);
    }
    __syncthreads();
    int tot=F1C*w;
    for(int o=tid;o<tot;o+=blockDim.x){
        int g=o/w, ni=o%w;
        int n=ni-l+(NL1-1);
        float re=0.f, im=0.f;
        #pragma unroll 8
        for(int j=0;j<NGRID;j++){
            float wk=sk1[g*NGRID+j];
            float2 kv=sK1[j*NM1+n];
            re=fmaf(wk,kv.x,re);
            im=fmaf(wk,kv.y,im);
        }
        size_t off=((size_t)l*FIN+f)*N1+o;
        g_Bre[off]=re;
        g_Bim[off]=im;
    }
}

// complex TN GEMM over packed per-l matrices
__global__ void k_cgemm(int layer){
    int l=blockIdx.z;
    int w=2*l+1;
    const float *Are,*Aim,*Bre,*Bim; float *Cre,*Cim;
    int Mst,Nst,Me,Ne,Ke;
    if(layer==0){
        Are=g_Are;Aim=g_Aim;Bre=g_Bre;Bim=g_Bim;Cre=g_Cre;Cim=g_Cim;
        Mst=M1;Nst=N1;Me=BATCH*w;Ne=F1C*w;Ke=K1D;
    } else {
        Are=g_A2re;Aim=g_A2im;Bre=g_B2re;Bim=g_B2im;Cre=g_C2re;Cim=g_C2im;
        Mst=M2;Nst=N2;Me=BATCH*w;Ne=F2C*w;Ke=F1C*w;
    }
    int m0=blockIdx.x*64, n0=blockIdx.y*64;
    if(m0>=Me||n0>=Ne) return;
    size_t Kst;
    const float* are=Are+(size_t)l*((layer==0)?(size_t)K1D*M1:(size_t)K2D*M2);
    const float* aim=Aim+(size_t)l*((layer==0)?(size_t)K1D*M1:(size_t)K2D*M2);
    const float* bre=Bre+(size_t)l*((layer==0)?(size_t)K1D*N1:(size_t)K2D*N2);
    const float* bim=Bim+(size_t)l*((layer==0)?(size_t)K1D*N1:(size_t)K2D*N2);
    float* cre=Cre+(size_t)l*((layer==0)?(size_t)M1*N1:(size_t)M2*N2);
    float* cim=Cim+(size_t)l*((layer==0)?(size_t)M1*N1:(size_t)M2*N2);
    (void)Kst;
    __shared__ __align__(16) float sAr[8][64],sAi[8][64],sBr[8][64],sBi[8][64];
    int tid=threadIdx.x; // 256
    int tx=tid&15, ty=tid>>4;
    float cr[4][4]={}, ci[4][4]={};
    for(int k0=0;k0<Ke;k0+=8){
        #pragma unroll
        for(int it=0;it<2;it++){
            int idx=tid+it*256;
            int kk=idx>>6, col=idx&63;
            int krow=k0+kk;
            float ar=0.f,ai=0.f,br=0.f,bi=0.f;
            if(krow<Ke){
                int mc=m0+col;
                if(mc<Me){ ar=are[(size_t)krow*Mst+mc]; ai=aim[(size_t)krow*Mst+mc]; }
                int nc=n0+col;
                if(nc<Ne){ br=bre[(size_t)krow*Nst+nc]; bi=bim[(size_t)krow*Nst+nc]; }
            }
            sAr[kk][col]=ar; sAi[kk][col]=ai;
            sBr[kk][col]=br; sBi[kk][col]=bi;
        }
        __syncthreads();
        #pragma unroll
        for(int kk=0;kk<8;kk++){
            float4 arv=*reinterpret_cast<const float4*>(&sAr[kk][ty*4]);
            float4 aiv=*reinterpret_cast<const float4*>(&sAi[kk][ty*4]);
            float4 brv=*reinterpret_cast<const float4*>(&sBr[kk][tx*4]);
            float4 biv=*reinterpret_cast<const float4*>(&sBi[kk][tx*4]);
            float ar[4]={arv.x,arv.y,arv.z,arv.w};
            float ai[4]={aiv.x,aiv.y,aiv.z,aiv.w};
            float br[4]={brv.x,brv.y,brv.z,brv.w};
            float bi[4]={biv.x,biv.y,biv.z,biv.w};
            #pragma unroll
            for(int i=0;i<4;i++)
                #pragma unroll
                for(int j=0;j<4;j++){
                    cr[i][j]=fmaf(ar[i],br[j],cr[i][j]);
                    cr[i][j]=fmaf(-ai[i],bi[j],cr[i][j]);
                    ci[i][j]=fmaf(ar[i],bi[j],ci[i][j]);
                    ci[i][j]=fmaf(ai[i],br[j],ci[i][j]);
                }
        }
        __syncthreads();
    }
    #pragma unroll
    for(int i=0;i<4;i++){
        int m=m0+ty*4+i;
        if(m>=Me) continue;
        #pragma unroll
        for(int j=0;j<4;j++){
            int n=n0+tx*4+j;
            if(n<Ne){
                cre[(size_t)m*Nst+n]=cr[i][j];
                cim[(size_t)m*Nst+n]=ci[i][j];
            }
        }
    }
}

// SO3 synthesis b1 + bias + relu -> x1[b,g,k,a,c]; reads packed C
__global__ void k_syn1(const float* __restrict__ bias1){
    int g=blockIdx.x, b=blockIdx.y;
    int tid=threadIdx.x; // 256
    __shared__ float2 sz[NL1*NM1*NM1];
    __shared__ float2 ssk[NM1*NM1];
    __shared__ float2 st[NA1*NM1];
    for(int i=tid;i<NL1*NM1*NM1;i+=blockDim.x) sz[i]=make_float2(0.f,0.f);
    __syncthreads();
    for(int i=tid;i<1330;i+=blockDim.x){
        int l=0;
        while(c_S10[l+1]<=i) l++;
        int r=i-c_S10[l], w=2*l+1;
        int mi=r/w, ni=r%w;
        int m=mi-l+(NL1-1), n=ni-l+(NL1-1);
        size_t off=((size_t)l*M1+b*w+mi)*N1+g*w+ni;
        sz[l*(NM1*NM1)+m*NM1+n]=make_float2(g_Cre[off],g_Cim[off]);
    }
    __syncthreads();
    float bv=bias1[g];
    for(int k=0;k<NA1;k++){
        for(int i=tid;i<NM1*NM1;i+=blockDim.x){
            float re=0.f, im=0.f;
            #pragma unroll
            for(int l=0;l<NL1;l++){
                float w=g_d4s1[(k*NL1+l)*(NM1*NM1)+i];
                float2 z=sz[l*(NM1*NM1)+i];
                re=fmaf(w,z.x,re);
                im=fmaf(w,z.y,im);
            }
            ssk[i]=make_float2(re,im);
        }
        __syncthreads();
        for(int i=tid;i<NA1*NM1;i+=blockDim.x){
            int a=i/NM1, n=i%NM1;
            float re=0.f, im=0.f;
            #pragma unroll
            for(int m=0;m<NM1;m++){
                float2 e=g_Es1[m*NA1+a];
                float2 s=ssk[m*NM1+n];
                re+=s.x*e.x-s.y*e.y;
                im+=s.x*e.y+s.y*e.x;
            }
            st[i]=make_float2(re,im);
        }
        __syncthreads();
        for(int i=tid;i<NA1*NA1;i+=blockDim.x){
            int a=i/NA1, c=i%NA1;
            float v=0.f;
            #pragma unroll
            for(int n=0;n<NM1;n++){
                float2 e=g_Es1[n*NA1+c];
                float2 t=st[a*NM1+n];
                v+=t.x*e.x-t.y*e.y;
            }
            v+=bv;
            v=v>0.f?v:0.f;
            g_x1[(((size_t)(b*F1C+g)*NA1+k)*NA1+a)*NA1+c]=v;
        }
        __syncthreads();
    }
}

// SO3 analysis b1 -> packed A2[l][ f*(2l+1)+pl ][ b*(2l+1)+ml ]
__global__ void k_t2(){
    int f=blockIdx.x, b=blockIdx.y;
    int tid=threadIdx.x; // 128
    __shared__ float  sx1[NA1*NA1];
    __shared__ float2 stt[NA1*NM2];
    __shared__ float2 su[NM2*NM2];
    __shared__ float2 sacc[NL2*NM2*NM2];
    for(int i=tid;i<NL2*NM2*NM2;i+=blockDim.x) sacc[i]=make_float2(0.f,0.f);
    __syncthreads();
    for(int k=0;k<NA1;k++){
        size_t xb=(((size_t)(b*F1C+f)*NA1+k))*NA1*NA1;
        for(int i=tid;i<NA1*NA1;i+=blockDim.x) sx1[i]=g_x1[xb+i];
        __syncthreads();
        for(int i=tid;i<NA1*NM2;i+=blockDim.x){
            int a=i/NM2, n=i%NM2;
            float re=0.f, im=0.f;
            #pragma unroll
            for(int c=0;c<NA1;c++){
                float xv=sx1[a*NA1+c];
                float2 e=g_Ea2[c*NM2+n];
                re=fmaf(xv,e.x,re);
                im=fmaf(xv,e.y,im);
            }
            stt[i]=make_float2(re,im);
        }
        __syncthreads();
        for(int i=tid;i<NM2*NM2;i+=blockDim.x){
            int m=i/NM2, n=i%NM2;
            float re=0.f, im=0.f;
            #pragma unroll
            for(int a=0;a<NA1;a++){
                float2 e=g_Ea2[a*NM2+m];
                float2 t=stt[a*NM2+n];
                re+=t.x*e.x-t.y*e.y;
                im+=t.x*e.y+t.y*e.x;
            }
            su[i]=make_float2(re,im);
        }
        __syncthreads();
        for(int i=tid;i<NL2*NM2*NM2;i+=blockDim.x){
            int l=i/(NM2*NM2), r=i%(NM2*NM2);
            float w=g_d4a2[(k*NL2+l)*(NM2*NM2)+r];
            float2 u=su[r];
            sacc[i].x=fmaf(w,u.x,sacc[i].x);
            sacc[i].y=fmaf(w,u.y,sacc[i].y);
        }
        __syncthreads();
    }
    for(int i=tid;i<286;i+=blockDim.x){
        int l=0;
        while(c_S6[l+1]<=i) l++;
        int r=i-c_S6[l], w=2*l+1;
        int ml=r/w, pl=r%w;
        int m=ml-l+(NL2-1), p=pl-l+(NL2-1);
        float2 v=sacc[l*(NM2*NM2)+m*NM2+p];
        size_t off=((size_t)l*K2D+f*w+pl)*M2+b*w+ml;
        g_A2re[off]=v.x;
        g_A2im[off]=v.y;
    }
}

// conj(yh2) -> packed B2[l][ f*(2l+1)+pl ][ g*(2l+1)+nl ]
__global__ void k_yh2(const float* __restrict__ kern2){
    int g=blockIdx.x, f=blockIdx.y;
    int tid=threadIdx.x; // 128
    __shared__ float skn[NK2];
    size_t kb=((size_t)f*F2C+g)*NK2;
    for(int i=tid;i<NK2;i+=blockDim.x) skn[i]=kern2[kb+i];
    __syncthreads();
    for(int i=tid;i<286;i+=blockDim.x){
        int l=0;
        while(c_S6[l+1]<=i) l++;
        int r=i-c_S6[l], w=2*l+1;
        int nl=r/w, pl=r%w;
        int n=nl-l+(NL2-1), p=pl-l+(NL2-1);
        float re=0.f, im=0.f;
        #pragma unroll 8
        for(int j=0;j<NK2;j++){
            float wk=skn[j];
            float2 kv=g_K2[(j*NL2+l)*(NM2*NM2)+n*NM2+p];
            re=fmaf(wk,kv.x,re);
            im=fmaf(wk,kv.y,im);
        }
        size_t off=((size_t)l*K2D+f*w+pl)*N2+g*w+nl;
        g_B2re[off]=re;
        g_B2im[off]=-im;
    }
}

// SO3 synthesis b2 + bias + relu + quadrature -> feat[b,g]; reads packed C2
__global__ void k_syn2(const float* __restrict__ bias2){
    int g=blockIdx.x, b=blockIdx.y;
    int tid=threadIdx.x; // 128
    __shared__ float2 sz[NL2*NM2*NM2];
    __shared__ float2 ss[NM2*NM2];
    __shared__ float2 st2[NA2*NM2];
    __shared__ float  sred[128];
    for(int i=tid;i<NL2*NM2*NM2;i+=blockDim.x) sz[i]=make_float2(0.f,0.f);
    __syncthreads();
    for(int i=tid;i<286;i+=blockDim.x){
        int l=0;
        while(c_S6[l+1]<=i) l++;
        int r=i-c_S6[l], w=2*l+1;
        int mi=r/w, ni=r%w;
        int m=mi-l+(NL2-1), n=ni-l+(NL2-1);
        size_t off=(size_t)l*M2*N2+((size_t)b*w+mi)*N2+g*w+ni;
        sz[l*(NM2*NM2)+m*NM2+n]=make_float2(g_C2re[off],g_C2im[off]);
    }
    __syncthreads();
    float bv=bias2[g];
    float acc=0.f;
    for(int k=0;k<NA2;k++){
        for(int i=tid;i<NM2*NM2;i+=blockDim.x){
            float re=0.f, im=0.f;
            #pragma unroll
            for(int l=0;l<NL2;l++){
                float w=g_d4s2[(k*NL2+l)*(NM2*NM2)+i];
                float2 z=sz[l*(NM2*NM2)+i];
                re=fmaf(w,z.x,re);
                im=fmaf(w,z.y,im);
            }
            ss[i]=make_float2(re,im);
        }
        __syncthreads();
        for(int i=tid;i<NA2*NM2;i+=blockDim.x){
            int a=i/NM2, n=i%NM2;
            float re=0.f, im=0.f;
            #pragma unroll
            for(int m=0;m<NM2;m++){
                float2 e=g_Es2[m*NA2+a];
                float2 s=ss[m*NM2+n];
                re+=s.x*e.x-s.y*e.y;
                im+=s.x*e.y+s.y*e.x;
            }
            st2[i]=make_float2(re,im);
        }
        __syncthreads();
        float wk=g_wint[k];
        for(int i=tid;i<NA2*NA2;i+=blockDim.x){
            int a=i/NA2, c=i%NA2;
            float v=0.f;
            #pragma unroll
            for(int n=0;n<NM2;n++){
                float2 e=g_Es2[n*NA2+c];
                float2 t=st2[a*NM2+n];
                v+=t.x*e.x-t.y*e.y;
            }
            v+=bv;
            v=v>0.f?v:0.f;
            acc+=wk*v;
        }
        __syncthreads();
    }
    sred[tid]=acc;
    __syncthreads();
    for(int s=64;s>0;s>>=1){
        if(tid<s) sred[tid]+=sred[tid+s];
        __syncthreads();
    }
    if(tid==0) g_feat[b*F2C+g]=sred[0];
}

__global__ void k_head(const float* __restrict__ W, const float* __restrict__ b_lin,
                       float* __restrict__ out){
    int idx=threadIdx.x;
    if(idx>=BATCH*2) return;
    int b=idx>>1, i=idx&1;
    float s=b_lin[i];
    #pragma unroll 8
    for(int g=0;g<F2C;g++) s+=g_feat[b*F2C+g]*W[i*F2C+g];
    out[idx]=s;
}

extern "C" void kernel_launch(void* const* d_in, const int* in_sizes, int n_in,
                              void* d_out, int out_size){
    const float* x     = (const float*)d_in[0];
    const float* kern1 = (const float*)d_in[1];
    const float* bias1 = (const float*)d_in[2];
    const float* kern2 = (const float*)d_in[3];
    const float* bias2 = (const float*)d_in[4];
    const float* W     = (const float*)d_in[5];
    const float* b_lin = (const float*)d_in[6];
    float* out = (float*)d_out;
    const int T=128;
    // order chosen so k_cgemm(layer 0) is launch #6 (ncu -s 5 -c 1 captures it)
    k_rng<<<1,32>>>();
    k_bas1<<<(NBIN*NL1*NM1+NBIN*NM1+T-1)/T,T>>>();
    k_bas_K1<<<(NGRID*NL1*NM1+T-1)/T,T>>>();
    k_xh<<<dim3(FIN,BATCH),192>>>(x);
    k_yh1<<<dim3(FIN,NL1),256>>>(kern1);
    k_cgemm<<<dim3((M1+63)/64,(N1+63)/64,NL1),256>>>(0);
    k_basA<<<(NA1*NL1*NM1*NM1+NM1*NA1+T-1)/T,T>>>();
    k_basB<<<(NA1*NL2*NM2*NM2+NA1*NM2+NK2*NL2*NM2*NM2+NA2*NL2*NM2*NM2+NM2*NA2+NA2+T-1)/T,T>>>();
    k_syn1<<<dim3(F1C,BATCH),256>>>(bias1);
    k_t2<<<dim3(F1C,BATCH),128>>>();
    k_yh2<<<dim3(F2C,F1C),128>>>(kern2);
    k_cgemm<<<dim3((M2+63)/64,(N2+63)/64,NL2),256>>>(1);
    k_syn2<<<dim3(F2C,BATCH),128>>>(bias2);
    k_head<<<1,128>>>(W,b_lin,out);
}

// round 14
// speedup vs baseline: 1.7410x; 1.2623x over previous
#include <cuda_runtime.h>
#include <math.h>

#define PI 3.14159265358979323846

#define NBIN 30
#define NM1 19
#define NL1 10
#define NA1 20
#define NM2 11
#define NL2 6
#define NA2 12
#define FIN 1029
#define F1C 20
#define F2C 40
#define BATCH 64
#define NGRID 128
#define NK2 144

#define M1 (BATCH*NM1)   // 1216 (row stride)
#define N1 (F1C*NM1)     // 380
#define K1D FIN          // 1029
#define M2 (BATCH*NM2)   // 704
#define N2 (F2C*NM2)     // 440
#define K2D (F1C*NM2)    // 220

// scratch
__device__ float g_Are[NL1*K1D*M1];
__device__ float g_Aim[NL1*K1D*M1];
__device__ float g_Bre[NL1*K1D*N1];
__device__ float g_Bim[NL1*K1D*N1];
__device__ float g_Cre[NL1*M1*N1];
__device__ float g_Cim[NL1*M1*N1];
__device__ float g_x1[BATCH*F1C*NA1*NA1*NA1];
__device__ float g_A2re[NL2*K2D*M2];
__device__ float g_A2im[NL2*K2D*M2];
__device__ float g_B2re[NL2*K2D*N2];
__device__ float g_B2im[NL2*K2D*N2];
__device__ float g_C2re[NL2*M2*N2];
__device__ float g_C2im[NL2*M2*N2];
__device__ float g_feat[BATCH*F2C];

// basis
__device__ float  g_d0w[NBIN*NL1*NM1];
__device__ float2 g_EaIN[NBIN*NM1];
__device__ float2 g_K1[NGRID*NL1*NM1];
__device__ float  g_d4s1[NA1*NL1*NM1*NM1];
__device__ float2 g_Es1[NM1*NA1];
__device__ float  g_d4a2[NA1*NL2*NM2*NM2];
__device__ float2 g_Ea2[NA1*NM2];
__device__ float2 g_K2[NK2*NL2*NM2*NM2];
__device__ float  g_d4s2[NA2*NL2*NM2*NM2];
__device__ float2 g_Es2[NM2*NA2];
__device__ float  g_wint[NA2];
__device__ double g_bg[NGRID];
__device__ double g_ag[NGRID];

__device__ __constant__ int c_S10[11] = {0,1,10,35,84,165,286,455,680,969,1330};
__device__ __constant__ int c_S6[7]   = {0,1,10,35,84,165,286};

__device__ __forceinline__ int imax(int a,int b){return a>b?a:b;}
__device__ __forceinline__ int imin(int a,int b){return a<b?a:b;}

__device__ __forceinline__ double dfact(int n){
    const double f[19] = {1.,1.,2.,6.,24.,120.,720.,5040.,40320.,362880.,3628800.,
        39916800.,479001600.,6227020800.,87178291200.,1307674368000.,
        20922789888000.,355687428096000.,6402373705728000.};
    return f[n];
}

__device__ double wigd(int l,int mp,int mm,double beta){
    double cb=cos(0.5*beta), sb=sin(0.5*beta);
    double pref=sqrt(dfact(l+mp)*dfact(l-mp)*dfact(l+mm)*dfact(l-mm));
    int s0=imax(0,mm-mp), s1=imin(l+mm,l-mp);
    double v=0.0;
    for(int s=s0;s<=s1;s++){
        double term=(((mp-mm+s)&1)?-1.0:1.0)
            /(dfact(l+mm-s)*dfact(s)*dfact(mp-mm+s)*dfact(l-mp-s));
        int ec=2*l+mm-mp-2*s, es=mp-mm+2*s;
        double cp=1.0; for(int t=0;t<ec;t++) cp*=cb;
        double sp=1.0; for(int t=0;t<es;t++) sp*=sb;
        v+=term*cp*sp;
    }
    return pref*v;
}

__device__ double dhw(int b,int k){
    double beta=PI*(2*k+1)/(4.0*b);
    double s=0.0;
    for(int j=0;j<b;j++) s+=sin(beta*(2*j+1))/(double)(2*j+1);
    return (2.0/b)*sin(beta)*s;
}

// numpy default_rng(42): SeedSequence -> PCG64 (xsl-rr-128/64)
__global__ void k_rng(){
    if(threadIdx.x!=0||blockIdx.x!=0) return;
    unsigned int pool[4];
    unsigned int hc=0x43b0d7e5u;
    auto hashmix=[&hc](unsigned int v){ v^=hc; hc*=0x931e8875u; v*=hc; v^=v>>16; return v; };
    pool[0]=hashmix(42u);
    for(int i=1;i<4;i++) pool[i]=hashmix(0u);
    for(int s=0;s<4;s++)
        for(int d=0;d<4;d++)
            if(s!=d){
                unsigned int h=hashmix(pool[s]);
                unsigned int r=pool[d]*0xca01f9ddu - h*0x4973f715u;
                r^=r>>16;
                pool[d]=r;
            }
    unsigned int hb=0x8b51f9ddu;
    unsigned int st32[8];
    for(int i=0;i<8;i++){
        unsigned int v=pool[i&3];
        v^=hb; hb*=0x58f38dedu; v*=hb; v^=v>>16;
        st32[i]=v;
    }
    unsigned long long w[4];
    for(int i=0;i<4;i++)
        w[i]=(unsigned long long)st32[2*i] | ((unsigned long long)st32[2*i+1]<<32);
    unsigned long long s_hi=w[0], s_lo=w[1];
    unsigned long long q_hi=w[2], q_lo=w[3];
    unsigned long long inc_hi=(q_hi<<1)|(q_lo>>63);
    unsigned long long inc_lo=(q_lo<<1)|1ull;
    const unsigned long long M_hi=0x2360ed051fc65da4ull, M_lo=0x4385df649fccf645ull;
    unsigned long long st_hi=0ull, st_lo=0ull;
    auto step=[&](){
        unsigned long long lo=st_lo*M_lo;
        unsigned long long hi=__umul64hi(st_lo,M_lo)+st_lo*M_hi+st_hi*M_lo;
        lo+=inc_lo;
        hi+=inc_hi+(lo<inc_lo?1ull:0ull);
        st_lo=lo; st_hi=hi;
    };
    step();
    { unsigned long long nl=st_lo+s_lo;
      st_hi+=s_hi+(nl<st_lo?1ull:0ull);
      st_lo=nl; }
    step();
    for(int i=0;i<2*NGRID;i++){
        step();
        unsigned long long xo=st_hi^st_lo;
        unsigned int rot=(unsigned int)(st_hi>>58);
        unsigned long long r64=(xo>>rot)|(xo<<((64u-rot)&63u));
        double u=(double)(r64>>11)*(1.0/9007199254740992.0);
        if(i<NGRID) g_bg[i]=acos(-1.0+2.0*u);
        else        g_ag[i-NGRID]=2.0*PI*u;
    }
}

__global__ void k_bas1(){
    int idx=blockIdx.x*blockDim.x+threadIdx.x;
    if(idx<NBIN*NL1*NM1){
        int k=idx/(NL1*NM1), l=(idx/NM1)%NL1, m=idx%NM1;
        int mv=m-(NL1-1);
        float v=0.f;
        if(mv>=-l&&mv<=l){
            double beta=PI*(2*k+1)/60.0;
            v=(float)(wigd(l,mv,0,beta)*dhw(15,k)/(4.0*PI));
        }
        g_d0w[idx]=v;
        return;
    }
    idx-=NBIN*NL1*NM1;
    if(idx<NBIN*NM1){
        int a=idx/NM1, m=idx%NM1;
        double th=(2.0*PI*a/NBIN)*(double)(m-(NL1-1));
        double sc=2.0*PI/NBIN;
        g_EaIN[idx]=make_float2((float)(cos(th)*sc),(float)(-sin(th)*sc));
    }
}
__global__ void k_bas_K1(){
    int idx=blockIdx.x*blockDim.x+threadIdx.x;
    if(idx>=NGRID*NL1*NM1) return;
    int j=idx/(NL1*NM1), l=(idx/NM1)%NL1, m=idx%NM1;
    int mv=m-(NL1-1);
    float2 v=make_float2(0.f,0.f);
    if(mv>=-l&&mv<=l){
        double d0=wigd(l,mv,0,g_bg[j]);
        double th=g_ag[j]*(double)mv;
        v=make_float2((float)(d0*cos(th)),(float)(-d0*sin(th)));
    }
    g_K1[idx]=v;
}
__global__ void k_basA(){
    int idx=blockIdx.x*blockDim.x+threadIdx.x;
    if(idx<NA1*NL1*NM1*NM1){
        int k=idx/(NL1*NM1*NM1), l=(idx/(NM1*NM1))%NL1;
        int m=(idx/NM1)%NM1, n=idx%NM1;
        int mv=m-(NL1-1), nv=n-(NL1-1);
        float v=0.f;
        if(mv>=-l&&mv<=l&&nv>=-l&&nv<=l){
            double beta=PI*(2*k+1)/40.0;
            v=(float)(wigd(l,mv,nv,beta)*(double)(2*l+1));
        }
        g_d4s1[idx]=v;
        return;
    }
    idx-=NA1*NL1*NM1*NM1;
    if(idx<NM1*NA1){
        int m=idx/NA1, a=idx%NA1;
        double th=(double)(m-(NL1-1))*(2.0*PI*a/NA1);
        g_Es1[idx]=make_float2((float)cos(th),(float)sin(th));
    }
}
__global__ void k_basB(){
    int idx=blockIdx.x*blockDim.x+threadIdx.x;
    if(idx<NA1*NL2*NM2*NM2){
        int k=idx/(NL2*NM2*NM2), l=(idx/(NM2*NM2))%NL2;
        int m=(idx/NM2)%NM2, n=idx%NM2;
        int mv=m-(NL2-1), nv=n-(NL2-1);
        float v=0.f;
        if(mv>=-l&&mv<=l&&nv>=-l&&nv<=l){
            double beta=PI*(2*k+1)/40.0;
            v=(float)(wigd(l,mv,nv,beta)*dhw(10,k)/(8.0*PI*PI));
        }
        g_d4a2[idx]=v;
        return;
    }
    idx-=NA1*NL2*NM2*NM2;
    if(idx<NA1*NM2){
        int a=idx/NM2, m=idx%NM2;
        double th=(2.0*PI*a/NA1)*(double)(m-(NL2-1));
        double sc=2.0*PI/NA1;
        g_Ea2[idx]=make_float2((float)(cos(th)*sc),(float)(-sin(th)*sc));
        return;
    }
    idx-=NA1*NM2;
    if(idx<NK2*NL2*NM2*NM2){
        int j=idx/(NL2*NM2*NM2), l=(idx/(NM2*NM2))%NL2;
        int m=(idx/NM2)%NM2, n=idx%NM2;
        int mv=m-(NL2-1), nv=n-(NL2-1);
        float2 v=make_float2(0.f,0.f);
        if(mv>=-l&&mv<=l&&nv>=-l&&nv<=l){
            int ib=j/48, ia=(j/6)%8, ig=j%6;
            double beta=(double)(ib+1)*(PI/8.0)/3.0;
            double alpha=2.0*PI*ia/8.0;
            double gamma=2.0*PI*ig/6.0;
            double d=wigd(l,mv,nv,beta);
            double th=alpha*(double)mv+gamma*(double)nv;
            v=make_float2((float)(d*cos(th)),(float)(-d*sin(th)));
        }
        g_K2[idx]=v;
        return;
    }
    idx-=NK2*NL2*NM2*NM2;
    if(idx<NA2*NL2*NM2*NM2){
        int k=idx/(NL2*NM2*NM2), l=(idx/(NM2*NM2))%NL2;
        int m=(idx/NM2)%NM2, n=idx%NM2;
        int mv=m-(NL2-1), nv=n-(NL2-1);
        float v=0.f;
        if(mv>=-l&&mv<=l&&nv>=-l&&nv<=l){
            double beta=PI*(2*k+1)/24.0;
            v=(float)(wigd(l,mv,nv,beta)*(double)(2*l+1));
        }
        g_d4s2[idx]=v;
        return;
    }
    idx-=NA2*NL2*NM2*NM2;
    if(idx<NM2*NA2){
        int m=idx/NA2, a=idx%NA2;
        double th=(double)(m-(NL2-1))*(2.0*PI*a/NA2);
        g_Es2[idx]=make_float2((float)cos(th),(float)sin(th));
        return;
    }
    idx-=NM2*NA2;
    if(idx<NA2){
        double sc=(2.0*PI/NA2)*(2.0*PI/NA2)/(8.0*PI*PI);
        g_wint[idx]=(float)(dhw(6,idx)*sc);
    }
}

// S2 analysis v2: 8 (b,f) rows per block, real-DFT symmetry (only m>=0 in stage 1),
// fused Wigner stage 2 in-block. Packed output A[l][f][ b*(2l+1)+mi ].
#define XH_PAIRS 8
__global__ void k_xh(const float* __restrict__ x){
    __shared__ float sbuf[XH_PAIRS*900];   // x rows, later e[p][k][mv]{re,im}
    __shared__ float2 sEa[NBIN*10];        // Ea for mv>=0: [a][mv]
    __shared__ float  sd0[NBIN*100];       // [k][lmi]
    int tid=threadIdx.x;                    // 256
    int r0=blockIdx.x*XH_PAIRS;             // flattened (b,f) row base
    size_t xbase=(size_t)r0*900;
    for(int i=tid;i<XH_PAIRS*900;i+=256) sbuf[i]=x[xbase+i];
    for(int i=tid;i<NBIN*10;i+=256){
        int a=i/10, mv=i%10;
        sEa[i]=g_EaIN[a*NM1+mv+(NL1-1)];
    }
    for(int i=tid;i<NBIN*100;i+=256){
        int k=i/100, lmi=i%100;
        int l=(int)sqrtf((float)lmi+0.5f);
        while(l*l>lmi) l--;
        while((l+1)*(l+1)<=lmi) l++;
        int mi=lmi-l*l;
        sd0[i]=g_d0w[(k*NL1+l)*NM1 + (mi-l+(NL1-1))];
    }
    __syncthreads();
    // stage 1: per (p,k), 10 non-negative m freqs
    float er[10], ei[10];
    int p=tid/NBIN, k=tid%NBIN;
    if(tid<XH_PAIRS*NBIN){
        float xr[NBIN];
        #pragma unroll
        for(int a=0;a<NBIN;a++) xr[a]=sbuf[p*900+k*NBIN+a];
        #pragma unroll
        for(int mv=0;mv<10;mv++){
            float re=0.f, im=0.f;
            #pragma unroll
            for(int a=0;a<NBIN;a++){
                float2 e=sEa[a*10+mv];
                re=fmaf(xr[a],e.x,re);
                im=fmaf(xr[a],e.y,im);
            }
            er[mv]=re; ei[mv]=im;
        }
    }
    __syncthreads();
    if(tid<XH_PAIRS*NBIN){
        #pragma unroll
        for(int mv=0;mv<10;mv++){
            sbuf[p*600+(k*10+mv)*2  ]=er[mv];
            sbuf[p*600+(k*10+mv)*2+1]=ei[mv];
        }
    }
    __syncthreads();
    // stage 2: 800 packed outputs
    for(int o=tid;o<XH_PAIRS*100;o+=256){
        int pp=o/100, lmi=o%100;
        int l=(int)sqrtf((float)lmi+0.5f);
        while(l*l>lmi) l--;
        while((l+1)*(l+1)<=lmi) l++;
        int mi=lmi-l*l;
        int mv=mi-l;
        int mabs=mv<0?-mv:mv;
        float sgn=mv<0?-1.f:1.f;
        float re=0.f, im=0.f;
        #pragma unroll 6
        for(int kk=0;kk<NBIN;kk++){
            float w=sd0[kk*100+lmi];
            re=fmaf(w,sbuf[pp*600+(kk*10+mabs)*2  ],re);
            im=fmaf(w,sbuf[pp*600+(kk*10+mabs)*2+1],im);
        }
        im*=sgn;
        int r=r0+pp;
        int b=r/FIN, f=r%FIN;
        size_t off=((size_t)l*FIN+f)*M1 + b*(2*l+1)+mi;
        g_Are[off]=re;
        g_Aim[off]=im;
    }
}

// conj(yh) with symmetry: yh[-n] = (-1)^n conj(yh[n]); packed B[l][f][ g*(2l+1)+ni ]
__global__ void k_yh1(const float* __restrict__ kern1){
    int f=blockIdx.x, l=blockIdx.y;
    int w=2*l+1;
    int tid=threadIdx.x; // 256
    __shared__ float  sk1[F1C*NGRID];
    __shared__ float2 sK1[NGRID*NM1];
    size_t kb=(size_t)f*F1C*NGRID;
    for(int i=tid;i<F1C*NGRID;i+=blockDim.x) sk1[i]=kern1[kb+i];
    for(int i=tid;i<NGRID*NM1;i+=blockDim.x){
        int j=i/NM1, n=i%NM1;
        float2 v=g_K1[(j*NL1+l)*NM1+n];
        sK1[i]=make_float2(v.x,-v.y);
    }
    __syncthreads();
    int tot=F1C*(l+1);
    for(int o=tid;o<tot;o+=blockDim.x){
        int g=o/(l+1), mv=o%(l+1);
        int n=mv+(NL1-1);
        float re=0.f, im=0.f;
        #pragma unroll 8
        for(int j=0;j<NGRID;j++){
            float wk=sk1[g*NGRID+j];
            float2 kv=sK1[j*NM1+n];
            re=fmaf(wk,kv.x,re);
            im=fmaf(wk,kv.y,im);
        }
        size_t ob=((size_t)l*FIN+f)*N1+g*w;
        g_Bre[ob+l+mv]=re;
        g_Bim[ob+l+mv]=im;
        if(mv>0){
            float s=(mv&1)?-1.f:1.f;
            g_Bre[ob+l-mv]=s*re;
            g_Bim[ob+l-mv]=-s*im;
        }
    }
}

// complex TN GEMM over packed per-l matrices
__global__ void k_cgemm(int layer){
    int l=blockIdx.z;
    int w=2*l+1;
    const float *Are,*Aim,*Bre,*Bim; float *Cre,*Cim;
    int Mst,Nst,Me,Ne,Ke;
    if(layer==0){
        Are=g_Are;Aim=g_Aim;Bre=g_Bre;Bim=g_Bim;Cre=g_Cre;Cim=g_Cim;
        Mst=M1;Nst=N1;Me=BATCH*w;Ne=F1C*w;Ke=K1D;
    } else {
        Are=g_A2re;Aim=g_A2im;Bre=g_B2re;Bim=g_B2im;Cre=g_C2re;Cim=g_C2im;
        Mst=M2;Nst=N2;Me=BATCH*w;Ne=F2C*w;Ke=F1C*w;
    }
    int m0=blockIdx.x*64, n0=blockIdx.y*64;
    if(m0>=Me||n0>=Ne) return;
    const float* are=Are+(size_t)l*((layer==0)?(size_t)K1D*M1:(size_t)K2D*M2);
    const float* aim=Aim+(size_t)l*((layer==0)?(size_t)K1D*M1:(size_t)K2D*M2);
    const float* bre=Bre+(size_t)l*((layer==0)?(size_t)K1D*N1:(size_t)K2D*N2);
    const float* bim=Bim+(size_t)l*((layer==0)?(size_t)K1D*N1:(size_t)K2D*N2);
    float* cre=Cre+(size_t)l*((layer==0)?(size_t)M1*N1:(size_t)M2*N2);
    float* cim=Cim+(size_t)l*((layer==0)?(size_t)M1*N1:(size_t)M2*N2);
    __shared__ __align__(16) float sAr[8][64],sAi[8][64],sBr[8][64],sBi[8][64];
    int tid=threadIdx.x; // 256
    int tx=tid&15, ty=tid>>4;
    float cr[4][4]={}, ci[4][4]={};
    for(int k0=0;k0<Ke;k0+=8){
        #pragma unroll
        for(int it=0;it<2;it++){
            int idx=tid+it*256;
            int kk=idx>>6, col=idx&63;
            int krow=k0+kk;
            float ar=0.f,ai=0.f,br=0.f,bi=0.f;
            if(krow<Ke){
                int mc=m0+col;
                if(mc<Me){ ar=are[(size_t)krow*Mst+mc]; ai=aim[(size_t)krow*Mst+mc]; }
                int nc=n0+col;
                if(nc<Ne){ br=bre[(size_t)krow*Nst+nc]; bi=bim[(size_t)krow*Nst+nc]; }
            }
            sAr[kk][col]=ar; sAi[kk][col]=ai;
            sBr[kk][col]=br; sBi[kk][col]=bi;
        }
        __syncthreads();
        #pragma unroll
        for(int kk=0;kk<8;kk++){
            float4 arv=*reinterpret_cast<const float4*>(&sAr[kk][ty*4]);
            float4 aiv=*reinterpret_cast<const float4*>(&sAi[kk][ty*4]);
            float4 brv=*reinterpret_cast<const float4*>(&sBr[kk][tx*4]);
            float4 biv=*reinterpret_cast<const float4*>(&sBi[kk][tx*4]);
            float ar[4]={arv.x,arv.y,arv.z,arv.w};
            float ai[4]={aiv.x,aiv.y,aiv.z,aiv.w};
            float br[4]={brv.x,brv.y,brv.z,brv.w};
            float bi[4]={biv.x,biv.y,biv.z,biv.w};
            #pragma unroll
            for(int i=0;i<4;i++)
                #pragma unroll
                for(int j=0;j<4;j++){
                    cr[i][j]=fmaf(ar[i],br[j],cr[i][j]);
                    cr[i][j]=fmaf(-ai[i],bi[j],cr[i][j]);
                    ci[i][j]=fmaf(ar[i],bi[j],ci[i][j]);
                    ci[i][j]=fmaf(ai[i],br[j],ci[i][j]);
                }
        }
        __syncthreads();
    }
    #pragma unroll
    for(int i=0;i<4;i++){
        int m=m0+ty*4+i;
        if(m>=Me) continue;
        #pragma unroll
        for(int j=0;j<4;j++){
            int n=n0+tx*4+j;
            if(n<Ne){
                cre[(size_t)m*Nst+n]=cr[i][j];
                cim[(size_t)m*Nst+n]=ci[i][j];
            }
        }
    }
}

// SO3 synthesis b1 + bias + relu -> x1[b,g,k,a,c]; reads packed C
__global__ void k_syn1(const float* __restrict__ bias1){
    int g=blockIdx.x, b=blockIdx.y;
    int tid=threadIdx.x; // 256
    __shared__ float2 sz[NL1*NM1*NM1];
    __shared__ float2 ssk[NM1*NM1];
    __shared__ float2 st[NA1*NM1];
    for(int i=tid;i<NL1*NM1*NM1;i+=blockDim.x) sz[i]=make_float2(0.f,0.f);
    __syncthreads();
    for(int i=tid;i<1330;i+=blockDim.x){
        int l=0;
        while(c_S10[l+1]<=i) l++;
        int r=i-c_S10[l], w=2*l+1;
        int mi=r/w, ni=r%w;
        int m=mi-l+(NL1-1), n=ni-l+(NL1-1);
        size_t off=((size_t)l*M1+b*w+mi)*N1+g*w+ni;
        sz[l*(NM1*NM1)+m*NM1+n]=make_float2(g_Cre[off],g_Cim[off]);
    }
    __syncthreads();
    float bv=bias1[g];
    for(int k=0;k<NA1;k++){
        for(int i=tid;i<NM1*NM1;i+=blockDim.x){
            float re=0.f, im=0.f;
            #pragma unroll
            for(int l=0;l<NL1;l++){
                float w=g_d4s1[(k*NL1+l)*(NM1*NM1)+i];
                float2 z=sz[l*(NM1*NM1)+i];
                re=fmaf(w,z.x,re);
                im=fmaf(w,z.y,im);
            }
            ssk[i]=make_float2(re,im);
        }
        __syncthreads();
        for(int i=tid;i<NA1*NM1;i+=blockDim.x){
            int a=i/NM1, n=i%NM1;
            float re=0.f, im=0.f;
            #pragma unroll
            for(int m=0;m<NM1;m++){
                float2 e=g_Es1[m*NA1+a];
                float2 s=ssk[m*NM1+n];
                re+=s.x*e.x-s.y*e.y;
                im+=s.x*e.y+s.y*e.x;
            }
            st[i]=make_float2(re,im);
        }
        __syncthreads();
        for(int i=tid;i<NA1*NA1;i+=blockDim.x){
            int a=i/NA1, c=i%NA1;
            float v=0.f;
            #pragma unroll
            for(int n=0;n<NM1;n++){
                float2 e=g_Es1[n*NA1+c];
                float2 t=st[a*NM1+n];
                v+=t.x*e.x-t.y*e.y;
            }
            v+=bv;
            v=v>0.f?v:0.f;
            g_x1[(((size_t)(b*F1C+g)*NA1+k)*NA1+a)*NA1+c]=v;
        }
        __syncthreads();
    }
}

// SO3 analysis b1 -> packed A2[l][ f*(2l+1)+pl ][ b*(2l+1)+ml ]
__global__ void k_t2(){
    int f=blockIdx.x, b=blockIdx.y;
    int tid=threadIdx.x; // 128
    __shared__ float  sx1[NA1*NA1];
    __shared__ float2 stt[NA1*NM2];
    __shared__ float2 su[NM2*NM2];
    __shared__ float2 sacc[NL2*NM2*NM2];
    for(int i=tid;i<NL2*NM2*NM2;i+=blockDim.x) sacc[i]=make_float2(0.f,0.f);
    __syncthreads();
    for(int k=0;k<NA1;k++){
        size_t xb=(((size_t)(b*F1C+f)*NA1+k))*NA1*NA1;
        for(int i=tid;i<NA1*NA1;i+=blockDim.x) sx1[i]=g_x1[xb+i];
        __syncthreads();
        for(int i=tid;i<NA1*NM2;i+=blockDim.x){
            int a=i/NM2, n=i%NM2;
            float re=0.f, im=0.f;
            #pragma unroll
            for(int c=0;c<NA1;c++){
                float xv=sx1[a*NA1+c];
                float2 e=g_Ea2[c*NM2+n];
                re=fmaf(xv,e.x,re);
                im=fmaf(xv,e.y,im);
            }
            stt[i]=make_float2(re,im);
        }
        __syncthreads();
        for(int i=tid;i<NM2*NM2;i+=blockDim.x){
            int m=i/NM2, n=i%NM2;
            float re=0.f, im=0.f;
            #pragma unroll
            for(int a=0;a<NA1;a++){
                float2 e=g_Ea2[a*NM2+m];
                float2 t=stt[a*NM2+n];
                re+=t.x*e.x-t.y*e.y;
                im+=t.x*e.y+t.y*e.x;
            }
            su[i]=make_float2(re,im);
        }
        __syncthreads();
        for(int i=tid;i<NL2*NM2*NM2;i+=blockDim.x){
            int l=i/(NM2*NM2), r=i%(NM2*NM2);
            float w=g_d4a2[(k*NL2+l)*(NM2*NM2)+r];
            float2 u=su[r];
            sacc[i].x=fmaf(w,u.x,sacc[i].x);
            sacc[i].y=fmaf(w,u.y,sacc[i].y);
        }
        __syncthreads();
    }
    for(int i=tid;i<286;i+=blockDim.x){
        int l=0;
        while(c_S6[l+1]<=i) l++;
        int r=i-c_S6[l], w=2*l+1;
        int ml=r/w, pl=r%w;
        int m=ml-l+(NL2-1), p=pl-l+(NL2-1);
        float2 v=sacc[l*(NM2*NM2)+m*NM2+p];
        size_t off=((size_t)l*K2D+f*w+pl)*M2+b*w+ml;
        g_A2re[off]=v.x;
        g_A2im[off]=v.y;
    }
}

// conj(yh2) -> packed B2[l][ f*(2l+1)+pl ][ g*(2l+1)+nl ]
__global__ void k_yh2(const float* __restrict__ kern2){
    int g=blockIdx.x, f=blockIdx.y;
    int tid=threadIdx.x; // 128
    __shared__ float skn[NK2];
    size_t kb=((size_t)f*F2C+g)*NK2;
    for(int i=tid;i<NK2;i+=blockDim.x) skn[i]=kern2[kb+i];
    __syncthreads();
    for(int i=tid;i<286;i+=blockDim.x){
        int l=0;
        while(c_S6[l+1]<=i) l++;
        int r=i-c_S6[l], w=2*l+1;
        int nl=r/w, pl=r%w;
        int n=nl-l+(NL2-1), p=pl-l+(NL2-1);
        float re=0.f, im=0.f;
        #pragma unroll 8
        for(int j=0;j<NK2;j++){
            float wk=skn[j];
            float2 kv=g_K2[(j*NL2+l)*(NM2*NM2)+n*NM2+p];
            re=fmaf(wk,kv.x,re);
            im=fmaf(wk,kv.y,im);
        }
        size_t off=((size_t)l*K2D+f*w+pl)*N2+g*w+nl;
        g_B2re[off]=re;
        g_B2im[off]=-im;
    }
}

// SO3 synthesis b2 + bias + relu + quadrature -> feat[b,g]; reads packed C2
__global__ void k_syn2(const float* __restrict__ bias2){
    int g=blockIdx.x, b=blockIdx.y;
    int tid=threadIdx.x; // 128
    __shared__ float2 sz[NL2*NM2*NM2];
    __shared__ float2 ss[NM2*NM2];
    __shared__ float2 st2[NA2*NM2];
    __shared__ float  sred[128];
    for(int i=tid;i<NL2*NM2*NM2;i+=blockDim.x) sz[i]=make_float2(0.f,0.f);
    __syncthreads();
    for(int i=tid;i<286;i+=blockDim.x){
        int l=0;
        while(c_S6[l+1]<=i) l++;
        int r=i-c_S6[l], w=2*l+1;
        int mi=r/w, ni=r%w;
        int m=mi-l+(NL2-1), n=ni-l+(NL2-1);
        size_t off=(size_t)l*M2*N2+((size_t)b*w+mi)*N2+g*w+ni;
        sz[l*(NM2*NM2)+m*NM2+n]=make_float2(g_C2re[off],g_C2im[off]);
    }
    __syncthreads();
    float bv=bias2[g];
    float acc=0.f;
    for(int k=0;k<NA2;k++){
        for(int i=tid;i<NM2*NM2;i+=blockDim.x){
            float re=0.f, im=0.f;
            #pragma unroll
            for(int l=0;l<NL2;l++){
                float w=g_d4s2[(k*NL2+l)*(NM2*NM2)+i];
                float2 z=sz[l*(NM2*NM2)+i];
                re=fmaf(w,z.x,re);
                im=fmaf(w,z.y,im);
            }
            ss[i]=make_float2(re,im);
        }
        __syncthreads();
        for(int i=tid;i<NA2*NM2;i+=blockDim.x){
            int a=i/NM2, n=i%NM2;
            float re=0.f, im=0.f;
            #pragma unroll
            for(int m=0;m<NM2;m++){
                float2 e=g_Es2[m*NA2+a];
                float2 s=ss[m*NM2+n];
                re+=s.x*e.x-s.y*e.y;
                im+=s.x*e.y+s.y*e.x;
            }
            st2[i]=make_float2(re,im);
        }
        __syncthreads();
        float wk=g_wint[k];
        for(int i=tid;i<NA2*NA2;i+=blockDim.x){
            int a=i/NA2, c=i%NA2;
            float v=0.f;
            #pragma unroll
            for(int n=0;n<NM2;n++){
                float2 e=g_Es2[n*NA2+c];
                float2 t=st2[a*NM2+n];
                v+=t.x*e.x-t.y*e.y;
            }
            v+=bv;
            v=v>0.f?v:0.f;
            acc+=wk*v;
        }
        __syncthreads();
    }
    sred[tid]=acc;
    __syncthreads();
    for(int s=64;s>0;s>>=1){
        if(tid<s) sred[tid]+=sred[tid+s];
        __syncthreads();
    }
    if(tid==0) g_feat[b*F2C+g]=sred[0];
}

__global__ void k_head(const float* __restrict__ W, const float* __restrict__ b_lin,
                       float* __restrict__ out){
    int idx=threadIdx.x;
    if(idx>=BATCH*2) return;
    int b=idx>>1, i=idx&1;
    float s=b_lin[i];
    #pragma unroll 8
    for(int g=0;g<F2C;g++) s+=g_feat[b*F2C+g]*W[i*F2C+g];
    out[idx]=s;
}

extern "C" void kernel_launch(void* const* d_in, const int* in_sizes, int n_in,
                              void* d_out, int out_size){
    const float* x     = (const float*)d_in[0];
    const float* kern1 = (const float*)d_in[1];
    const float* bias1 = (const float*)d_in[2];
    const float* kern2 = (const float*)d_in[3];
    const float* bias2 = (const float*)d_in[4];
    const float* W     = (const float*)d_in[5];
    const float* b_lin = (const float*)d_in[6];
    float* out = (float*)d_out;
    const int T=128;
    k_rng<<<1,32>>>();
    k_bas1<<<(NBIN*NL1*NM1+NBIN*NM1+T-1)/T,T>>>();
    k_bas_K1<<<(NGRID*NL1*NM1+T-1)/T,T>>>();
    k_xh<<<(BATCH*FIN)/XH_PAIRS,256>>>(x);
    k_yh1<<<dim3(FIN,NL1),256>>>(kern1);
    k_cgemm<<<dim3((M1+63)/64,(N1+63)/64,NL1),256>>>(0);
    k_basA<<<(NA1*NL1*NM1*NM1+NM1*NA1+T-1)/T,T>>>();
    k_basB<<<(NA1*NL2*NM2*NM2+NA1*NM2+NK2*NL2*NM2*NM2+NA2*NL2*NM2*NM2+NM2*NA2+NA2+T-1)/T,T>>>();
    k_syn1<<<dim3(F1C,BATCH),256>>>(bias1);
    k_t2<<<dim3(F1C,BATCH),128>>>();
    k_yh2<<<dim3(F2C,F1C),128>>>(kern2);
    k_cgemm<<<dim3((M2+63)/64,(N2+63)/64,NL2),256>>>(1);
    k_syn2<<<dim3(F2C,BATCH),128>>>(bias2);
    k_head<<<1,128>>>(W,b_lin,out);
}

// round 15
// speedup vs baseline: 2.0248x; 1.1630x over previous
#include <cuda_runtime.h>
#include <math.h>

#define PI 3.14159265358979323846

#define NBIN 30
#define NM1 19
#define NL1 10
#define NA1 20
#define NM2 11
#define NL2 6
#define NA2 12
#define FIN 1029
#define F1C 20
#define F2C 40
#define BATCH 64
#define NGRID 128
#define NK2 144

#define N1 (F1C*NM1)     // 380
#define K1D FIN          // 1029
#define N2 (F2C*NM2)     // 440
#define K2D (F1C*NM2)    // 220
#define M1H (BATCH*NL1)  // 640  (half-M packed row stride, layer 1)
#define M2H (BATCH*NL2)  // 384  (half-M packed row stride, layer 2)

// scratch
__device__ float g_Are[NL1*K1D*M1H];
__device__ float g_Aim[NL1*K1D*M1H];
__device__ float g_Bre[NL1*K1D*N1];
__device__ float g_Bim[NL1*K1D*N1];
__device__ float g_Cre[NL1*M1H*N1];
__device__ float g_Cim[NL1*M1H*N1];
__device__ float g_x1[BATCH*F1C*NA1*NA1*NA1];
__device__ float g_A2re[NL2*K2D*M2H];
__device__ float g_A2im[NL2*K2D*M2H];
__device__ float g_B2re[NL2*K2D*N2];
__device__ float g_B2im[NL2*K2D*N2];
__device__ float g_C2re[NL2*M2H*N2];
__device__ float g_C2im[NL2*M2H*N2];
__device__ float g_feat[BATCH*F2C];

// basis
__device__ float  g_d0w[NBIN*NL1*NM1];
__device__ float2 g_EaIN[NBIN*NM1];
__device__ float2 g_K1[NGRID*NL1*NM1];
__device__ float  g_d4s1[NA1*NL1*NM1*NM1];
__device__ float2 g_Es1[NM1*NA1];
__device__ float  g_d4a2[NA1*NL2*NM2*NM2];
__device__ float2 g_Ea2[NA1*NM2];
__device__ float2 g_K2[NK2*NL2*NM2*NM2];
__device__ float  g_d4s2[NA2*NL2*NM2*NM2];
__device__ float2 g_Es2[NM2*NA2];
__device__ float  g_wint[NA2];
__device__ double g_bg[NGRID];
__device__ double g_ag[NGRID];

__device__ __constant__ int c_S10[11] = {0,1,10,35,84,165,286,455,680,969,1330};
__device__ __constant__ int c_S6[7]   = {0,1,10,35,84,165,286};
__device__ __constant__ int c_T10[11] = {0,1,3,6,10,15,21,28,36,45,55};   // sum (l+1)
__device__ __constant__ int c_H6[7]   = {0,1,7,22,50,95,161};             // sum (l+1)(2l+1)

__device__ __forceinline__ int imax(int a,int b){return a>b?a:b;}
__device__ __forceinline__ int imin(int a,int b){return a<b?a:b;}

__device__ __forceinline__ double dfact(int n){
    const double f[19] = {1.,1.,2.,6.,24.,120.,720.,5040.,40320.,362880.,3628800.,
        39916800.,479001600.,6227020800.,87178291200.,1307674368000.,
        20922789888000.,355687428096000.,6402373705728000.};
    return f[n];
}

__device__ double wigd(int l,int mp,int mm,double beta){
    double cb=cos(0.5*beta), sb=sin(0.5*beta);
    double pref=sqrt(dfact(l+mp)*dfact(l-mp)*dfact(l+mm)*dfact(l-mm));
    int s0=imax(0,mm-mp), s1=imin(l+mm,l-mp);
    double v=0.0;
    for(int s=s0;s<=s1;s++){
        double term=(((mp-mm+s)&1)?-1.0:1.0)
            /(dfact(l+mm-s)*dfact(s)*dfact(mp-mm+s)*dfact(l-mp-s));
        int ec=2*l+mm-mp-2*s, es=mp-mm+2*s;
        double cp=1.0; for(int t=0;t<ec;t++) cp*=cb;
        double sp=1.0; for(int t=0;t<es;t++) sp*=sb;
        v+=term*cp*sp;
    }
    return pref*v;
}

__device__ double dhw(int b,int k){
    double beta=PI*(2*k+1)/(4.0*b);
    double s=0.0;
    for(int j=0;j<b;j++) s+=sin(beta*(2*j+1))/(double)(2*j+1);
    return (2.0/b)*sin(beta)*s;
}

// numpy default_rng(42): SeedSequence -> PCG64 (xsl-rr-128/64)
__global__ void k_rng(){
    if(threadIdx.x!=0||blockIdx.x!=0) return;
    unsigned int pool[4];
    unsigned int hc=0x43b0d7e5u;
    auto hashmix=[&hc](unsigned int v){ v^=hc; hc*=0x931e8875u; v*=hc; v^=v>>16; return v; };
    pool[0]=hashmix(42u);
    for(int i=1;i<4;i++) pool[i]=hashmix(0u);
    for(int s=0;s<4;s++)
        for(int d=0;d<4;d++)
            if(s!=d){
                unsigned int h=hashmix(pool[s]);
                unsigned int r=pool[d]*0xca01f9ddu - h*0x4973f715u;
                r^=r>>16;
                pool[d]=r;
            }
    unsigned int hb=0x8b51f9ddu;
    unsigned int st32[8];
    for(int i=0;i<8;i++){
        unsigned int v=pool[i&3];
        v^=hb; hb*=0x58f38dedu; v*=hb; v^=v>>16;
        st32[i]=v;
    }
    unsigned long long w[4];
    for(int i=0;i<4;i++)
        w[i]=(unsigned long long)st32[2*i] | ((unsigned long long)st32[2*i+1]<<32);
    unsigned long long s_hi=w[0], s_lo=w[1];
    unsigned long long q_hi=w[2], q_lo=w[3];
    unsigned long long inc_hi=(q_hi<<1)|(q_lo>>63);
    unsigned long long inc_lo=(q_lo<<1)|1ull;
    const unsigned long long M_hi=0x2360ed051fc65da4ull, M_lo=0x4385df649fccf645ull;
    unsigned long long st_hi=0ull, st_lo=0ull;
    auto step=[&](){
        unsigned long long lo=st_lo*M_lo;
        unsigned long long hi=__umul64hi(st_lo,M_lo)+st_lo*M_hi+st_hi*M_lo;
        lo+=inc_lo;
        hi+=inc_hi+(lo<inc_lo?1ull:0ull);
        st_lo=lo; st_hi=hi;
    };
    step();
    { unsigned long long nl=st_lo+s_lo;
      st_hi+=s_hi+(nl<st_lo?1ull:0ull);
      st_lo=nl; }
    step();
    for(int i=0;i<2*NGRID;i++){
        step();
        unsigned long long xo=st_hi^st_lo;
        unsigned int rot=(unsigned int)(st_hi>>58);
        unsigned long long r64=(xo>>rot)|(xo<<((64u-rot)&63u));
        double u=(double)(r64>>11)*(1.0/9007199254740992.0);
        if(i<NGRID) g_bg[i]=acos(-1.0+2.0*u);
        else        g_ag[i-NGRID]=2.0*PI*u;
    }
}

__global__ void k_bas1(){
    int idx=blockIdx.x*blockDim.x+threadIdx.x;
    if(idx<NBIN*NL1*NM1){
        int k=idx/(NL1*NM1), l=(idx/NM1)%NL1, m=idx%NM1;
        int mv=m-(NL1-1);
        float v=0.f;
        if(mv>=-l&&mv<=l){
            double beta=PI*(2*k+1)/60.0;
            v=(float)(wigd(l,mv,0,beta)*dhw(15,k)/(4.0*PI));
        }
        g_d0w[idx]=v;
        return;
    }
    idx-=NBIN*NL1*NM1;
    if(idx<NBIN*NM1){
        int a=idx/NM1, m=idx%NM1;
        double th=(2.0*PI*a/NBIN)*(double)(m-(NL1-1));
        double sc=2.0*PI/NBIN;
        g_EaIN[idx]=make_float2((float)(cos(th)*sc),(float)(-sin(th)*sc));
    }
}
__global__ void k_bas_K1(){
    int idx=blockIdx.x*blockDim.x+threadIdx.x;
    if(idx>=NGRID*NL1*NM1) return;
    int j=idx/(NL1*NM1), l=(idx/NM1)%NL1, m=idx%NM1;
    int mv=m-(NL1-1);
    float2 v=make_float2(0.f,0.f);
    if(mv>=-l&&mv<=l){
        double d0=wigd(l,mv,0,g_bg[j]);
        double th=g_ag[j]*(double)mv;
        v=make_float2((float)(d0*cos(th)),(float)(-d0*sin(th)));
    }
    g_K1[idx]=v;
}
__global__ void k_basA(){
    int idx=blockIdx.x*blockDim.x+threadIdx.x;
    if(idx<NA1*NL1*NM1*NM1){
        int k=idx/(NL1*NM1*NM1), l=(idx/(NM1*NM1))%NL1;
        int m=(idx/NM1)%NM1, n=idx%NM1;
        int mv=m-(NL1-1), nv=n-(NL1-1);
        float v=0.f;
        if(mv>=-l&&mv<=l&&nv>=-l&&nv<=l){
            double beta=PI*(2*k+1)/40.0;
            v=(float)(wigd(l,mv,nv,beta)*(double)(2*l+1));
        }
        g_d4s1[idx]=v;
        return;
    }
    idx-=NA1*NL1*NM1*NM1;
    if(idx<NM1*NA1){
        int m=idx/NA1, a=idx%NA1;
        double th=(double)(m-(NL1-1))*(2.0*PI*a/NA1);
        g_Es1[idx]=make_float2((float)cos(th),(float)sin(th));
    }
}
__global__ void k_basB(){
    int idx=blockIdx.x*blockDim.x+threadIdx.x;
    if(idx<NA1*NL2*NM2*NM2){
        int k=idx/(NL2*NM2*NM2), l=(idx/(NM2*NM2))%NL2;
        int m=(idx/NM2)%NM2, n=idx%NM2;
        int mv=m-(NL2-1), nv=n-(NL2-1);
        float v=0.f;
        if(mv>=-l&&mv<=l&&nv>=-l&&nv<=l){
            double beta=PI*(2*k+1)/40.0;
            v=(float)(wigd(l,mv,nv,beta)*dhw(10,k)/(8.0*PI*PI));
        }
        g_d4a2[idx]=v;
        return;
    }
    idx-=NA1*NL2*NM2*NM2;
    if(idx<NA1*NM2){
        int a=idx/NM2, m=idx%NM2;
        double th=(2.0*PI*a/NA1)*(double)(m-(NL2-1));
        double sc=2.0*PI/NA1;
        g_Ea2[idx]=make_float2((float)(cos(th)*sc),(float)(-sin(th)*sc));
        return;
    }
    idx-=NA1*NM2;
    if(idx<NK2*NL2*NM2*NM2){
        int j=idx/(NL2*NM2*NM2), l=(idx/(NM2*NM2))%NL2;
        int m=(idx/NM2)%NM2, n=idx%NM2;
        int mv=m-(NL2-1), nv=n-(NL2-1);
        float2 v=make_float2(0.f,0.f);
        if(mv>=-l&&mv<=l&&nv>=-l&&nv<=l){
            int ib=j/48, ia=(j/6)%8, ig=j%6;
            double beta=(double)(ib+1)*(PI/8.0)/3.0;
            double alpha=2.0*PI*ia/8.0;
            double gamma=2.0*PI*ig/6.0;
            double d=wigd(l,mv,nv,beta);
            double th=alpha*(double)mv+gamma*(double)nv;
            v=make_float2((float)(d*cos(th)),(float)(-d*sin(th)));
        }
        g_K2[idx]=v;
        return;
    }
    idx-=NK2*NL2*NM2*NM2;
    if(idx<NA2*NL2*NM2*NM2){
        int k=idx/(NL2*NM2*NM2), l=(idx/(NM2*NM2))%NL2;
        int m=(idx/NM2)%NM2, n=idx%NM2;
        int mv=m-(NL2-1), nv=n-(NL2-1);
        float v=0.f;
        if(mv>=-l&&mv<=l&&nv>=-l&&nv<=l){
            double beta=PI*(2*k+1)/24.0;
            v=(float)(wigd(l,mv,nv,beta)*(double)(2*l+1));
        }
        g_d4s2[idx]=v;
        return;
    }
    idx-=NA2*NL2*NM2*NM2;
    if(idx<NM2*NA2){
        int m=idx/NA2, a=idx%NA2;
        double th=(double)(m-(NL2-1))*(2.0*PI*a/NA2);
        g_Es2[idx]=make_float2((float)cos(th),(float)sin(th));
        return;
    }
    idx-=NM2*NA2;
    if(idx<NA2){
        double sc=(2.0*PI/NA2)*(2.0*PI/NA2)/(8.0*PI*PI);
        g_wint[idx]=(float)(dhw(6,idx)*sc);
    }
}

// S2 analysis: half-M packed A[l][f][ b*(l+1)+mv ], mv >= 0 only.
#define XH_PAIRS 8
__global__ void k_xh(const float* __restrict__ x){
    __shared__ float sbuf[XH_PAIRS*900];   // x rows, later e[p][k][mv]{re,im}
    __shared__ float2 sEa[NBIN*10];        // Ea for mv>=0
    __shared__ float  sd0[NBIN*55];        // [k][hm] weights for mv>=0
    int tid=threadIdx.x;                    // 256
    int r0=blockIdx.x*XH_PAIRS;
    size_t xbase=(size_t)r0*900;
    for(int i=tid;i<XH_PAIRS*900;i+=256) sbuf[i]=x[xbase+i];
    for(int i=tid;i<NBIN*10;i+=256){
        int a=i/10, mv=i%10;
        sEa[i]=g_EaIN[a*NM1+mv+(NL1-1)];
    }
    for(int i=tid;i<NBIN*55;i+=256){
        int k=i/55, hm=i%55;
        int l=0;
        while(c_T10[l+1]<=hm) l++;
        int mv=hm-c_T10[l];
        sd0[i]=g_d0w[(k*NL1+l)*NM1 + mv+(NL1-1)];
    }
    __syncthreads();
    float er[10], ei[10];
    int p=tid/NBIN, k=tid%NBIN;
    if(tid<XH_PAIRS*NBIN){
        float xr[NBIN];
        #pragma unroll
        for(int a=0;a<NBIN;a++) xr[a]=sbuf[p*900+k*NBIN+a];
        #pragma unroll
        for(int mv=0;mv<10;mv++){
            float re=0.f, im=0.f;
            #pragma unroll
            for(int a=0;a<NBIN;a++){
                float2 e=sEa[a*10+mv];
                re=fmaf(xr[a],e.x,re);
                im=fmaf(xr[a],e.y,im);
            }
            er[mv]=re; ei[mv]=im;
        }
    }
    __syncthreads();
    if(tid<XH_PAIRS*NBIN){
        #pragma unroll
        for(int mv=0;mv<10;mv++){
            sbuf[p*600+(k*10+mv)*2  ]=er[mv];
            sbuf[p*600+(k*10+mv)*2+1]=ei[mv];
        }
    }
    __syncthreads();
    for(int o=tid;o<XH_PAIRS*55;o+=256){
        int pp=o/55, hm=o%55;
        int l=0;
        while(c_T10[l+1]<=hm) l++;
        int mv=hm-c_T10[l];
        float re=0.f, im=0.f;
        #pragma unroll 6
        for(int kk=0;kk<NBIN;kk++){
            float w=sd0[kk*55+hm];
            re=fmaf(w,sbuf[pp*600+(kk*10+mv)*2  ],re);
            im=fmaf(w,sbuf[pp*600+(kk*10+mv)*2+1],im);
        }
        int r=r0+pp;
        int b=r/FIN, f=r%FIN;
        size_t off=((size_t)l*FIN+f)*M1H + b*(l+1)+mv;
        g_Are[off]=re;
        g_Aim[off]=im;
    }
}

// conj(yh) full-width B (with n-symmetry to halve the reduction work)
__global__ void k_yh1(const float* __restrict__ kern1){
    int f=blockIdx.x, l=blockIdx.y;
    int w=2*l+1;
    int tid=threadIdx.x; // 256
    __shared__ float  sk1[F1C*NGRID];
    __shared__ float2 sK1[NGRID*NM1];
    size_t kb=(size_t)f*F1C*NGRID;
    for(int i=tid;i<F1C*NGRID;i+=blockDim.x) sk1[i]=kern1[kb+i];
    for(int i=tid;i<NGRID*NM1;i+=blockDim.x){
        int j=i/NM1, n=i%NM1;
        float2 v=g_K1[(j*NL1+l)*NM1+n];
        sK1[i]=make_float2(v.x,-v.y);
    }
    __syncthreads();
    int tot=F1C*(l+1);
    for(int o=tid;o<tot;o+=blockDim.x){
        int g=o/(l+1), mv=o%(l+1);
        int n=mv+(NL1-1);
        float re=0.f, im=0.f;
        #pragma unroll 8
        for(int j=0;j<NGRID;j++){
            float wk=sk1[g*NGRID+j];
            float2 kv=sK1[j*NM1+n];
            re=fmaf(wk,kv.x,re);
            im=fmaf(wk,kv.y,im);
        }
        size_t ob=((size_t)l*FIN+f)*N1+g*w;
        g_Bre[ob+l+mv]=re;
        g_Bim[ob+l+mv]=im;
        if(mv>0){
            float s=(mv&1)?-1.f:1.f;
            g_Bre[ob+l-mv]=s*re;
            g_Bim[ob+l-mv]=-s*im;
        }
    }
}

// complex TN GEMM over packed per-l matrices (half-M rows)
__global__ void k_cgemm(int layer){
    int l=blockIdx.z;
    int w=2*l+1;
    const float *Are,*Aim,*Bre,*Bim; float *Cre,*Cim;
    int Mst,Nst,Me,Ne,Ke;
    size_t pa,pb,pc;
    if(layer==0){
        Are=g_Are;Aim=g_Aim;Bre=g_Bre;Bim=g_Bim;Cre=g_Cre;Cim=g_Cim;
        Mst=M1H;Nst=N1;Me=BATCH*(l+1);Ne=F1C*w;Ke=K1D;
        pa=(size_t)l*K1D*M1H; pb=(size_t)l*K1D*N1; pc=(size_t)l*M1H*N1;
    } else {
        Are=g_A2re;Aim=g_A2im;Bre=g_B2re;Bim=g_B2im;Cre=g_C2re;Cim=g_C2im;
        Mst=M2H;Nst=N2;Me=BATCH*(l+1);Ne=F2C*w;Ke=F1C*w;
        pa=(size_t)l*K2D*M2H; pb=(size_t)l*K2D*N2; pc=(size_t)l*M2H*N2;
    }
    int m0=blockIdx.x*64, n0=blockIdx.y*64;
    if(m0>=Me||n0>=Ne) return;
    const float* are=Are+pa;
    const float* aim=Aim+pa;
    const float* bre=Bre+pb;
    const float* bim=Bim+pb;
    float* cre=Cre+pc;
    float* cim=Cim+pc;
    __shared__ __align__(16) float sAr[8][64],sAi[8][64],sBr[8][64],sBi[8][64];
    int tid=threadIdx.x; // 256
    int tx=tid&15, ty=tid>>4;
    float cr[4][4]={}, ci[4][4]={};
    for(int k0=0;k0<Ke;k0+=8){
        #pragma unroll
        for(int it=0;it<2;it++){
            int idx=tid+it*256;
            int kk=idx>>6, col=idx&63;
            int krow=k0+kk;
            float ar=0.f,ai=0.f,br=0.f,bi=0.f;
            if(krow<Ke){
                int mc=m0+col;
                if(mc<Me){ ar=are[(size_t)krow*Mst+mc]; ai=aim[(size_t)krow*Mst+mc]; }
                int nc=n0+col;
                if(nc<Ne){ br=bre[(size_t)krow*Nst+nc]; bi=bim[(size_t)krow*Nst+nc]; }
            }
            sAr[kk][col]=ar; sAi[kk][col]=ai;
            sBr[kk][col]=br; sBi[kk][col]=bi;
        }
        __syncthreads();
        #pragma unroll
        for(int kk=0;kk<8;kk++){
            float4 arv=*reinterpret_cast<const float4*>(&sAr[kk][ty*4]);
            float4 aiv=*reinterpret_cast<const float4*>(&sAi[kk][ty*4]);
            float4 brv=*reinterpret_cast<const float4*>(&sBr[kk][tx*4]);
            float4 biv=*reinterpret_cast<const float4*>(&sBi[kk][tx*4]);
            float ar[4]={arv.x,arv.y,arv.z,arv.w};
            float ai[4]={aiv.x,aiv.y,aiv.z,aiv.w};
            float br[4]={brv.x,brv.y,brv.z,brv.w};
            float bi[4]={biv.x,biv.y,biv.z,biv.w};
            #pragma unroll
            for(int i=0;i<4;i++)
                #pragma unroll
                for(int j=0;j<4;j++){
                    cr[i][j]=fmaf(ar[i],br[j],cr[i][j]);
                    cr[i][j]=fmaf(-ai[i],bi[j],cr[i][j]);
                    ci[i][j]=fmaf(ar[i],bi[j],ci[i][j]);
                    ci[i][j]=fmaf(ai[i],br[j],ci[i][j]);
                }
        }
        __syncthreads();
    }
    #pragma unroll
    for(int i=0;i<4;i++){
        int m=m0+ty*4+i;
        if(m>=Me) continue;
        #pragma unroll
        for(int j=0;j<4;j++){
            int n=n0+tx*4+j;
            if(n<Ne){
                cre[(size_t)m*Nst+n]=cr[i][j];
                cim[(size_t)m*Nst+n]=ci[i][j];
            }
        }
    }
}

// SO3 synthesis b1: reconstruct m<0 via C[-m,-n]=(-1)^{m+n}conj(C[m,n])
__global__ void k_syn1(const float* __restrict__ bias1){
    int g=blockIdx.x, b=blockIdx.y;
    int tid=threadIdx.x; // 256
    __shared__ float2 sz[NL1*NM1*NM1];
    __shared__ float2 ssk[NM1*NM1];
    __shared__ float2 st[NA1*NM1];
    for(int i=tid;i<NL1*NM1*NM1;i+=blockDim.x) sz[i]=make_float2(0.f,0.f);
    __syncthreads();
    for(int i=tid;i<1330;i+=blockDim.x){
        int l=0;
        while(c_S10[l+1]<=i) l++;
        int r=i-c_S10[l], w=2*l+1;
        int mi=r/w, ni=r%w;
        int mv=mi-l;
        float2 v;
        if(mv>=0){
            size_t off=(size_t)l*M1H*N1+((size_t)b*(l+1)+mv)*N1+g*w+ni;
            v=make_float2(g_Cre[off],g_Cim[off]);
        } else {
            size_t off=(size_t)l*M1H*N1+((size_t)b*(l+1)+(-mv))*N1+g*w+(w-1-ni);
            float s=((mi+ni)&1)?-1.f:1.f;
            v=make_float2(s*g_Cre[off],-s*g_Cim[off]);
        }
        int m=mi-l+(NL1-1), n=ni-l+(NL1-1);
        sz[l*(NM1*NM1)+m*NM1+n]=v;
    }
    __syncthreads();
    float bv=bias1[g];
    for(int k=0;k<NA1;k++){
        for(int i=tid;i<NM1*NM1;i+=blockDim.x){
            float re=0.f, im=0.f;
            #pragma unroll
            for(int l=0;l<NL1;l++){
                float w=g_d4s1[(k*NL1+l)*(NM1*NM1)+i];
                float2 z=sz[l*(NM1*NM1)+i];
                re=fmaf(w,z.x,re);
                im=fmaf(w,z.y,im);
            }
            ssk[i]=make_float2(re,im);
        }
        __syncthreads();
        for(int i=tid;i<NA1*NM1;i+=blockDim.x){
            int a=i/NM1, n=i%NM1;
            float re=0.f, im=0.f;
            #pragma unroll
            for(int m=0;m<NM1;m++){
                float2 e=g_Es1[m*NA1+a];
                float2 s=ssk[m*NM1+n];
                re+=s.x*e.x-s.y*e.y;
                im+=s.x*e.y+s.y*e.x;
            }
            st[i]=make_float2(re,im);
        }
        __syncthreads();
        for(int i=tid;i<NA1*NA1;i+=blockDim.x){
            int a=i/NA1, c=i%NA1;
            float v=0.f;
            #pragma unroll
            for(int n=0;n<NM1;n++){
                float2 e=g_Es1[n*NA1+c];
                float2 t=st[a*NM1+n];
                v+=t.x*e.x-t.y*e.y;
            }
            v+=bv;
            v=v>0.f?v:0.f;
            g_x1[(((size_t)(b*F1C+g)*NA1+k)*NA1+a)*NA1+c]=v;
        }
        __syncthreads();
    }
}

// SO3 analysis b1 -> half-M packed A2[l][ f*(2l+1)+pl ][ b*(l+1)+mv ]
__global__ void k_t2(){
    int f=blockIdx.x, b=blockIdx.y;
    int tid=threadIdx.x; // 128
    __shared__ float  sx1[NA1*NA1];
    __shared__ float2 stt[NA1*NM2];
    __shared__ float2 su[NM2*NM2];
    __shared__ float2 sacc[NL2*NM2*NM2];
    for(int i=tid;i<NL2*NM2*NM2;i+=blockDim.x) sacc[i]=make_float2(0.f,0.f);
    __syncthreads();
    for(int k=0;k<NA1;k++){
        size_t xb=(((size_t)(b*F1C+f)*NA1+k))*NA1*NA1;
        for(int i=tid;i<NA1*NA1;i+=blockDim.x) sx1[i]=g_x1[xb+i];
        __syncthreads();
        for(int i=tid;i<NA1*NM2;i+=blockDim.x){
            int a=i/NM2, n=i%NM2;
            float re=0.f, im=0.f;
            #pragma unroll
            for(int c=0;c<NA1;c++){
                float xv=sx1[a*NA1+c];
                float2 e=g_Ea2[c*NM2+n];
                re=fmaf(xv,e.x,re);
                im=fmaf(xv,e.y,im);
            }
            stt[i]=make_float2(re,im);
        }
        __syncthreads();
        for(int i=tid;i<NM2*NM2;i+=blockDim.x){
            int m=i/NM2, n=i%NM2;
            float re=0.f, im=0.f;
            #pragma unroll
            for(int a=0;a<NA1;a++){
                float2 e=g_Ea2[a*NM2+m];
                float2 t=stt[a*NM2+n];
                re+=t.x*e.x-t.y*e.y;
                im+=t.x*e.y+t.y*e.x;
            }
            su[i]=make_float2(re,im);
        }
        __syncthreads();
        for(int i=tid;i<NL2*NM2*NM2;i+=blockDim.x){
            int l=i/(NM2*NM2), r=i%(NM2*NM2);
            float w=g_d4a2[(k*NL2+l)*(NM2*NM2)+r];
            float2 u=su[r];
            sacc[i].x=fmaf(w,u.x,sacc[i].x);
            sacc[i].y=fmaf(w,u.y,sacc[i].y);
        }
        __syncthreads();
    }
    for(int i=tid;i<161;i+=blockDim.x){
        int l=0;
        while(c_H6[l+1]<=i) l++;
        int r=i-c_H6[l], w=2*l+1;
        int mv=r/w, pl=r%w;                      // mv in 0..l, pl full 0..2l
        int m=mv+(NL2-1), p=pl-l+(NL2-1);
        float2 v=sacc[l*(NM2*NM2)+m*NM2+p];
        size_t off=((size_t)l*K2D+f*w+pl)*M2H+b*(l+1)+mv;
        g_A2re[off]=v.x;
        g_A2im[off]=v.y;
    }
}

// conj(yh2) -> full packed B2[l][ f*(2l+1)+pl ][ g*(2l+1)+nl ]
__global__ void k_yh2(const float* __restrict__ kern2){
    int g=blockIdx.x, f=blockIdx.y;
    int tid=threadIdx.x; // 128
    __shared__ float skn[NK2];
    size_t kb=((size_t)f*F2C+g)*NK2;
    for(int i=tid;i<NK2;i+=blockDim.x) skn[i]=kern2[kb+i];
    __syncthreads();
    for(int i=tid;i<286;i+=blockDim.x){
        int l=0;
        while(c_S6[l+1]<=i) l++;
        int r=i-c_S6[l], w=2*l+1;
        int nl=r/w, pl=r%w;
        int n=nl-l+(NL2-1), p=pl-l+(NL2-1);
        float re=0.f, im=0.f;
        #pragma unroll 8
        for(int j=0;j<NK2;j++){
            float wk=skn[j];
            float2 kv=g_K2[(j*NL2+l)*(NM2*NM2)+n*NM2+p];
            re=fmaf(wk,kv.x,re);
            im=fmaf(wk,kv.y,im);
        }
        size_t off=((size_t)l*K2D+f*w+pl)*N2+g*w+nl;
        g_B2re[off]=re;
        g_B2im[off]=-im;
    }
}

// SO3 synthesis b2: reconstruct m<0 from half C2
__global__ void k_syn2(const float* __restrict__ bias2){
    int g=blockIdx.x, b=blockIdx.y;
    int tid=threadIdx.x; // 128
    __shared__ float2 sz[NL2*NM2*NM2];
    __shared__ float2 ss[NM2*NM2];
    __shared__ float2 st2[NA2*NM2];
    __shared__ float  sred[128];
    for(int i=tid;i<NL2*NM2*NM2;i+=blockDim.x) sz[i]=make_float2(0.f,0.f);
    __syncthreads();
    for(int i=tid;i<286;i+=blockDim.x){
        int l=0;
        while(c_S6[l+1]<=i) l++;
        int r=i-c_S6[l], w=2*l+1;
        int mi=r/w, ni=r%w;
        int mv=mi-l;
        float2 v;
        if(mv>=0){
            size_t off=(size_t)l*M2H*N2+((size_t)b*(l+1)+mv)*N2+g*w+ni;
            v=make_float2(g_C2re[off],g_C2im[off]);
        } else {
            size_t off=(size_t)l*M2H*N2+((size_t)b*(l+1)+(-mv))*N2+g*w+(w-1-ni);
            float s=((mi+ni)&1)?-1.f:1.f;
            v=make_float2(s*g_C2re[off],-s*g_C2im[off]);
        }
        int m=mi-l+(NL2-1), n=ni-l+(NL2-1);
        sz[l*(NM2*NM2)+m*NM2+n]=v;
    }
    __syncthreads();
    float bv=bias2[g];
    float acc=0.f;
    for(int k=0;k<NA2;k++){
        for(int i=tid;i<NM2*NM2;i+=blockDim.x){
            float re=0.f, im=0.f;
            #pragma unroll
            for(int l=0;l<NL2;l++){
                float w=g_d4s2[(k*NL2+l)*(NM2*NM2)+i];
                float2 z=sz[l*(NM2*NM2)+i];
                re=fmaf(w,z.x,re);
                im=fmaf(w,z.y,im);
            }
            ss[i]=make_float2(re,im);
        }
        __syncthreads();
        for(int i=tid;i<NA2*NM2;i+=blockDim.x){
            int a=i/NM2, n=i%NM2;
            float re=0.f, im=0.f;
            #pragma unroll
            for(int m=0;m<NM2;m++){
                float2 e=g_Es2[m*NA2+a];
                float2 s=ss[m*NM2+n];
                re+=s.x*e.x-s.y*e.y;
                im+=s.x*e.y+s.y*e.x;
            }
            st2[i]=make_float2(re,im);
        }
        __syncthreads();
        float wk=g_wint[k];
        for(int i=tid;i<NA2*NA2;i+=blockDim.x){
            int a=i/NA2, c=i%NA2;
            float v=0.f;
            #pragma unroll
            for(int n=0;n<NM2;n++){
                float2 e=g_Es2[n*NA2+c];
                float2 t=st2[a*NM2+n];
                v+=t.x*e.x-t.y*e.y;
            }
            v+=bv;
            v=v>0.f?v:0.f;
            acc+=wk*v;
        }
        __syncthreads();
    }
    sred[tid]=acc;
    __syncthreads();
    for(int s=64;s>0;s>>=1){
        if(tid<s) sred[tid]+=sred[tid+s];
        __syncthreads();
    }
    if(tid==0) g_feat[b*F2C+g]=sred[0];
}

__global__ void k_head(const float* __restrict__ W, const float* __restrict__ b_lin,
                       float* __restrict__ out){
    int idx=threadIdx.x;
    if(idx>=BATCH*2) return;
    int b=idx>>1, i=idx&1;
    float s=b_lin[i];
    #pragma unroll 8
    for(int g=0;g<F2C;g++) s+=g_feat[b*F2C+g]*W[i*F2C+g];
    out[idx]=s;
}

extern "C" void kernel_launch(void* const* d_in, const int* in_sizes, int n_in,
                              void* d_out, int out_size){
    const float* x     = (const float*)d_in[0];
    const float* kern1 = (const float*)d_in[1];
    const float* bias1 = (const float*)d_in[2];
    const float* kern2 = (const float*)d_in[3];
    const float* bias2 = (const float*)d_in[4];
    const float* W     = (const float*)d_in[5];
    const float* b_lin = (const float*)d_in[6];
    float* out = (float*)d_out;
    const int T=128;
    k_rng<<<1,32>>>();
    k_bas1<<<(NBIN*NL1*NM1+NBIN*NM1+T-1)/T,T>>>();
    k_bas_K1<<<(NGRID*NL1*NM1+T-1)/T,T>>>();
    k_xh<<<(BATCH*FIN)/XH_PAIRS,256>>>(x);
    k_yh1<<<dim3(FIN,NL1),256>>>(kern1);
    k_cgemm<<<dim3(10,6,NL1),256>>>(0);
    k_basA<<<(NA1*NL1*NM1*NM1+NM1*NA1+T-1)/T,T>>>();
    k_basB<<<(NA1*NL2*NM2*NM2+NA1*NM2+NK2*NL2*NM2*NM2+NA2*NL2*NM2*NM2+NM2*NA2+NA2+T-1)/T,T>>>();
    k_syn1<<<dim3(F1C,BATCH),256>>>(bias1);
    k_t2<<<dim3(F1C,BATCH),128>>>();
    k_yh2<<<dim3(F2C,F1C),128>>>(kern2);
    k_cgemm<<<dim3(6,7,NL2),256>>>(1);
    k_syn2<<<dim3(F2C,BATCH),128>>>(bias2);
    k_head<<<1,128>>>(W,b_lin,out);
}

// round 16
// speedup vs baseline: 2.4102x; 1.1903x over previous
#include <cuda_runtime.h>
#include <math.h>

#define PI 3.14159265358979323846

#define NBIN 30
#define NM1 19
#define NL1 10
#define NA1 20
#define NM2 11
#define NL2 6
#define NA2 12
#define FIN 1029
#define F1C 20
#define F2C 40
#define BATCH 64
#define NGRID 128
#define NK2 144

#define N1 (F1C*NM1)     // 380
#define K1D FIN          // 1029
#define N2 (F2C*NM2)     // 440
#define K2D (F1C*NM2)    // 220
#define M1H (BATCH*NL1)  // 640
#define M2H (BATCH*NL2)  // 384
#define C1SZ (NL1*M1H*N1)   // 2,432,000

// scratch
__device__ float g_Are[NL1*K1D*M1H];
__device__ float g_Aim[NL1*K1D*M1H];
__device__ float g_Bre[NL1*K1D*N1];
__device__ float g_Bim[NL1*K1D*N1];
__device__ float g_Cre[C1SZ];
__device__ float g_Cim[C1SZ];
__device__ float g_x1[BATCH*F1C*NA1*NA1*NA1];   // also partial-C buffer during GEMM1
__device__ float g_A2re[NL2*K2D*M2H];
__device__ float g_A2im[NL2*K2D*M2H];
__device__ float g_B2re[NL2*K2D*N2];
__device__ float g_B2im[NL2*K2D*N2];
__device__ float g_C2re[NL2*M2H*N2];
__device__ float g_C2im[NL2*M2H*N2];
__device__ float g_feat[BATCH*F2C];

// basis
__device__ float  g_d0w[NBIN*NL1*NM1];
__device__ float2 g_EaIN[NBIN*NM1];
__device__ float2 g_K1[NGRID*NL1*NM1];
__device__ float  g_d4s1[NA1*NL1*NM1*NM1];
__device__ float2 g_Es1[NM1*NA1];
__device__ float  g_d4a2[NA1*NL2*NM2*NM2];
__device__ float2 g_Ea2[NA1*NM2];
__device__ float2 g_K2[NK2*NL2*NM2*NM2];
__device__ float  g_d4s2[NA2*NL2*NM2*NM2];
__device__ float2 g_Es2[NM2*NA2];
__device__ float  g_wint[NA2];
__device__ double g_bg[NGRID];
__device__ double g_ag[NGRID];

__device__ __constant__ int c_S10[11] = {0,1,10,35,84,165,286,455,680,969,1330};
__device__ __constant__ int c_S6[7]   = {0,1,10,35,84,165,286};
__device__ __constant__ int c_T10[11] = {0,1,3,6,10,15,21,28,36,45,55};
__device__ __constant__ int c_H6[7]   = {0,1,7,22,50,95,161};

__device__ __forceinline__ int imax(int a,int b){return a>b?a:b;}
__device__ __forceinline__ int imin(int a,int b){return a<b?a:b;}

__device__ __forceinline__ double dfact(int n){
    const double f[19] = {1.,1.,2.,6.,24.,120.,720.,5040.,40320.,362880.,3628800.,
        39916800.,479001600.,6227020800.,87178291200.,1307674368000.,
        20922789888000.,355687428096000.,6402373705728000.};
    return f[n];
}

__device__ double wigd(int l,int mp,int mm,double beta){
    double cb=cos(0.5*beta), sb=sin(0.5*beta);
    double pref=sqrt(dfact(l+mp)*dfact(l-mp)*dfact(l+mm)*dfact(l-mm));
    int s0=imax(0,mm-mp), s1=imin(l+mm,l-mp);
    double v=0.0;
    for(int s=s0;s<=s1;s++){
        double term=(((mp-mm+s)&1)?-1.0:1.0)
            /(dfact(l+mm-s)*dfact(s)*dfact(mp-mm+s)*dfact(l-mp-s));
        int ec=2*l+mm-mp-2*s, es=mp-mm+2*s;
        double cp=1.0; for(int t=0;t<ec;t++) cp*=cb;
        double sp=1.0; for(int t=0;t<es;t++) sp*=sb;
        v+=term*cp*sp;
    }
    return pref*v;
}

__device__ double dhw(int b,int k){
    double beta=PI*(2*k+1)/(4.0*b);
    double s=0.0;
    for(int j=0;j<b;j++) s+=sin(beta*(2*j+1))/(double)(2*j+1);
    return (2.0/b)*sin(beta)*s;
}

// ---- 128-bit helpers for PCG64 jump-ahead ----
struct U128{ unsigned long long hi,lo; };
__device__ __forceinline__ U128 u128mul(U128 a,U128 b){
    U128 r;
    r.lo=a.lo*b.lo;
    r.hi=__umul64hi(a.lo,b.lo)+a.lo*b.hi+a.hi*b.lo;
    return r;
}
__device__ __forceinline__ U128 u128add(U128 a,U128 b){
    U128 r;
    r.lo=a.lo+b.lo;
    r.hi=a.hi+b.hi+(r.lo<a.lo?1ull:0ull);
    return r;
}

// numpy default_rng(42): SeedSequence -> PCG64, parallel via LCG jump-ahead.
// Thread i computes draw i (bit-identical to the serial loop).
__global__ void k_rng(){
    int tid=threadIdx.x;            // 256 threads = 256 draws
    // SeedSequence(42) pool mixing (redundant per thread; cheap)
    unsigned int pool[4];
    unsigned int hc=0x43b0d7e5u;
    auto hashmix=[&hc](unsigned int v){ v^=hc; hc*=0x931e8875u; v*=hc; v^=v>>16; return v; };
    pool[0]=hashmix(42u);
    for(int i=1;i<4;i++) pool[i]=hashmix(0u);
    for(int s=0;s<4;s++)
        for(int d=0;d<4;d++)
            if(s!=d){
                unsigned int h=hashmix(pool[s]);
                unsigned int r=pool[d]*0xca01f9ddu - h*0x4973f715u;
                r^=r>>16;
                pool[d]=r;
            }
    unsigned int hb=0x8b51f9ddu;
    unsigned int st32[8];
    for(int i=0;i<8;i++){
        unsigned int v=pool[i&3];
        v^=hb; hb*=0x58f38dedu; v*=hb; v^=v>>16;
        st32[i]=v;
    }
    unsigned long long w[4];
    for(int i=0;i<4;i++)
        w[i]=(unsigned long long)st32[2*i] | ((unsigned long long)st32[2*i+1]<<32);
    U128 S  ={w[0],w[1]};
    U128 INC={(w[2]<<1)|(w[3]>>63),(w[3]<<1)|1ull};
    U128 M  ={0x2360ed051fc65da4ull,0x4385df649fccf645ull};
    // s2 = T(T(0)+S), T(x)=M*x+INC
    U128 st={0ull,0ull};
    st=u128add(u128mul(st,M),INC);       // s1
    st=u128add(st,S);
    st=u128add(u128mul(st,M),INC);       // s2
    // advance by delta = tid+1 : state' = am*st + ap
    U128 am={0ull,1ull}, ap={0ull,0ull}, cm=M, cp=INC;
    unsigned int d=(unsigned int)(tid+1);
    U128 one={0ull,1ull};
    while(d){
        if(d&1u){
            ap=u128add(u128mul(ap,cm),cp);
            am=u128mul(am,cm);
        }
        cp=u128mul(u128add(cm,one),cp);
        cm=u128mul(cm,cm);
        d>>=1;
    }
    st=u128add(u128mul(st,am),ap);
    // xsl-rr output
    unsigned long long xo=st.hi^st.lo;
    unsigned int rot=(unsigned int)(st.hi>>58);
    unsigned long long r64=(xo>>rot)|(xo<<((64u-rot)&63u));
    double u=(double)(r64>>11)*(1.0/9007199254740992.0);
    if(tid<NGRID) g_bg[tid]=acos(-1.0+2.0*u);
    else if(tid<2*NGRID) g_ag[tid-NGRID]=2.0*PI*u;
}

__global__ void k_bas1(){
    int idx=blockIdx.x*blockDim.x+threadIdx.x;
    if(idx<NBIN*NL1*NM1){
        int k=idx/(NL1*NM1), l=(idx/NM1)%NL1, m=idx%NM1;
        int mv=m-(NL1-1);
        float v=0.f;
        if(mv>=-l&&mv<=l){
            double beta=PI*(2*k+1)/60.0;
            v=(float)(wigd(l,mv,0,beta)*dhw(15,k)/(4.0*PI));
        }
        g_d0w[idx]=v;
        return;
    }
    idx-=NBIN*NL1*NM1;
    if(idx<NBIN*NM1){
        int a=idx/NM1, m=idx%NM1;
        double th=(2.0*PI*a/NBIN)*(double)(m-(NL1-1));
        double sc=2.0*PI/NBIN;
        g_EaIN[idx]=make_float2((float)(cos(th)*sc),(float)(-sin(th)*sc));
    }
}
__global__ void k_bas_K1(){
    int idx=blockIdx.x*blockDim.x+threadIdx.x;
    if(idx>=NGRID*NL1*NM1) return;
    int j=idx/(NL1*NM1), l=(idx/NM1)%NL1, m=idx%NM1;
    int mv=m-(NL1-1);
    float2 v=make_float2(0.f,0.f);
    if(mv>=-l&&mv<=l){
        double d0=wigd(l,mv,0,g_bg[j]);
        double th=g_ag[j]*(double)mv;
        v=make_float2((float)(d0*cos(th)),(float)(-d0*sin(th)));
    }
    g_K1[idx]=v;
}
__global__ void k_basA(){
    int idx=blockIdx.x*blockDim.x+threadIdx.x;
    if(idx<NA1*NL1*NM1*NM1){
        int k=idx/(NL1*NM1*NM1), l=(idx/(NM1*NM1))%NL1;
        int m=(idx/NM1)%NM1, n=idx%NM1;
        int mv=m-(NL1-1), nv=n-(NL1-1);
        float v=0.f;
        if(mv>=-l&&mv<=l&&nv>=-l&&nv<=l){
            double beta=PI*(2*k+1)/40.0;
            v=(float)(wigd(l,mv,nv,beta)*(double)(2*l+1));
        }
        g_d4s1[idx]=v;
        return;
    }
    idx-=NA1*NL1*NM1*NM1;
    if(idx<NM1*NA1){
        int m=idx/NA1, a=idx%NA1;
        double th=(double)(m-(NL1-1))*(2.0*PI*a/NA1);
        g_Es1[idx]=make_float2((float)cos(th),(float)sin(th));
    }
}
__global__ void k_basB(){
    int idx=blockIdx.x*blockDim.x+threadIdx.x;
    if(idx<NA1*NL2*NM2*NM2){
        int k=idx/(NL2*NM2*NM2), l=(idx/(NM2*NM2))%NL2;
        int m=(idx/NM2)%NM2, n=idx%NM2;
        int mv=m-(NL2-1), nv=n-(NL2-1);
        float v=0.f;
        if(mv>=-l&&mv<=l&&nv>=-l&&nv<=l){
            double beta=PI*(2*k+1)/40.0;
            v=(float)(wigd(l,mv,nv,beta)*dhw(10,k)/(8.0*PI*PI));
        }
        g_d4a2[idx]=v;
        return;
    }
    idx-=NA1*NL2*NM2*NM2;
    if(idx<NA1*NM2){
        int a=idx/NM2, m=idx%NM2;
        double th=(2.0*PI*a/NA1)*(double)(m-(NL2-1));
        double sc=2.0*PI/NA1;
        g_Ea2[idx]=make_float2((float)(cos(th)*sc),(float)(-sin(th)*sc));
        return;
    }
    idx-=NA1*NM2;
    if(idx<NK2*NL2*NM2*NM2){
        int j=idx/(NL2*NM2*NM2), l=(idx/(NM2*NM2))%NL2;
        int m=(idx/NM2)%NM2, n=idx%NM2;
        int mv=m-(NL2-1), nv=n-(NL2-1);
        float2 v=make_float2(0.f,0.f);
        if(mv>=-l&&mv<=l&&nv>=-l&&nv<=l){
            int ib=j/48, ia=(j/6)%8, ig=j%6;
            double beta=(double)(ib+1)*(PI/8.0)/3.0;
            double alpha=2.0*PI*ia/8.0;
            double gamma=2.0*PI*ig/6.0;
            double dd=wigd(l,mv,nv,beta);
            double th=alpha*(double)mv+gamma*(double)nv;
            v=make_float2((float)(dd*cos(th)),(float)(-dd*sin(th)));
        }
        g_K2[idx]=v;
        return;
    }
    idx-=NK2*NL2*NM2*NM2;
    if(idx<NA2*NL2*NM2*NM2){
        int k=idx/(NL2*NM2*NM2), l=(idx/(NM2*NM2))%NL2;
        int m=(idx/NM2)%NM2, n=idx%NM2;
        int mv=m-(NL2-1), nv=n-(NL2-1);
        float v=0.f;
        if(mv>=-l&&mv<=l&&nv>=-l&&nv<=l){
            double beta=PI*(2*k+1)/24.0;
            v=(float)(wigd(l,mv,nv,beta)*(double)(2*l+1));
        }
        g_d4s2[idx]=v;
        return;
    }
    idx-=NA2*NL2*NM2*NM2;
    if(idx<NM2*NA2){
        int m=idx/NA2, a=idx%NA2;
        double th=(double)(m-(NL2-1))*(2.0*PI*a/NA2);
        g_Es2[idx]=make_float2((float)cos(th),(float)sin(th));
        return;
    }
    idx-=NM2*NA2;
    if(idx<NA2){
        double sc=(2.0*PI/NA2)*(2.0*PI/NA2)/(8.0*PI*PI);
        g_wint[idx]=(float)(dhw(6,idx)*sc);
    }
}

// S2 analysis: half-M packed A[l][f][ b*(l+1)+mv ], mv >= 0 only.
#define XH_PAIRS 8
__global__ void k_xh(const float* __restrict__ x){
    __shared__ float sbuf[XH_PAIRS*900];
    __shared__ float2 sEa[NBIN*10];
    __shared__ float  sd0[NBIN*55];
    int tid=threadIdx.x;                    // 256
    int r0=blockIdx.x*XH_PAIRS;
    size_t xbase=(size_t)r0*900;
    for(int i=tid;i<XH_PAIRS*900;i+=256) sbuf[i]=x[xbase+i];
    for(int i=tid;i<NBIN*10;i+=256){
        int a=i/10, mv=i%10;
        sEa[i]=g_EaIN[a*NM1+mv+(NL1-1)];
    }
    for(int i=tid;i<NBIN*55;i+=256){
        int k=i/55, hm=i%55;
        int l=0;
        while(c_T10[l+1]<=hm) l++;
        int mv=hm-c_T10[l];
        sd0[i]=g_d0w[(k*NL1+l)*NM1 + mv+(NL1-1)];
    }
    __syncthreads();
    float er[10], ei[10];
    int p=tid/NBIN, k=tid%NBIN;
    if(tid<XH_PAIRS*NBIN){
        float xr[NBIN];
        #pragma unroll
        for(int a=0;a<NBIN;a++) xr[a]=sbuf[p*900+k*NBIN+a];
        #pragma unroll
        for(int mv=0;mv<10;mv++){
            float re=0.f, im=0.f;
            #pragma unroll
            for(int a=0;a<NBIN;a++){
                float2 e=sEa[a*10+mv];
                re=fmaf(xr[a],e.x,re);
                im=fmaf(xr[a],e.y,im);
            }
            er[mv]=re; ei[mv]=im;
        }
    }
    __syncthreads();
    if(tid<XH_PAIRS*NBIN){
        #pragma unroll
        for(int mv=0;mv<10;mv++){
            sbuf[p*600+(k*10+mv)*2  ]=er[mv];
            sbuf[p*600+(k*10+mv)*2+1]=ei[mv];
        }
    }
    __syncthreads();
    for(int o=tid;o<XH_PAIRS*55;o+=256){
        int pp=o/55, hm=o%55;
        int l=0;
        while(c_T10[l+1]<=hm) l++;
        int mv=hm-c_T10[l];
        float re=0.f, im=0.f;
        #pragma unroll 6
        for(int kk=0;kk<NBIN;kk++){
            float w=sd0[kk*55+hm];
            re=fmaf(w,sbuf[pp*600+(kk*10+mv)*2  ],re);
            im=fmaf(w,sbuf[pp*600+(kk*10+mv)*2+1],im);
        }
        int r=r0+pp;
        int b=r/FIN, f=r%FIN;
        size_t off=((size_t)l*FIN+f)*M1H + b*(l+1)+mv;
        g_Are[off]=re;
        g_Aim[off]=im;
    }
}

// conj(yh) full-width B (n-symmetry halves the reduction)
__global__ void k_yh1(const float* __restrict__ kern1){
    int f=blockIdx.x, l=blockIdx.y;
    int w=2*l+1;
    int tid=threadIdx.x; // 256
    __shared__ float  sk1[F1C*NGRID];
    __shared__ float2 sK1[NGRID*NM1];
    size_t kb=(size_t)f*F1C*NGRID;
    for(int i=tid;i<F1C*NGRID;i+=blockDim.x) sk1[i]=kern1[kb+i];
    for(int i=tid;i<NGRID*NM1;i+=blockDim.x){
        int j=i/NM1, n=i%NM1;
        float2 v=g_K1[(j*NL1+l)*NM1+n];
        sK1[i]=make_float2(v.x,-v.y);
    }
    __syncthreads();
    int tot=F1C*(l+1);
    for(int o=tid;o<tot;o+=blockDim.x){
        int g=o/(l+1), mv=o%(l+1);
        int n=mv+(NL1-1);
        float re=0.f, im=0.f;
        #pragma unroll 8
        for(int j=0;j<NGRID;j++){
            float wk=sk1[g*NGRID+j];
            float2 kv=sK1[j*NM1+n];
            re=fmaf(wk,kv.x,re);
            im=fmaf(wk,kv.y,im);
        }
        size_t ob=((size_t)l*FIN+f)*N1+g*w;
        g_Bre[ob+l+mv]=re;
        g_Bim[ob+l+mv]=im;
        if(mv>0){
            float s=(mv&1)?-1.f:1.f;
            g_Bre[ob+l-mv]=s*re;
            g_Bim[ob+l-mv]=-s*im;
        }
    }
}

// complex TN GEMM over packed per-l matrices (half-M rows), K-split chunks
__global__ void k_cgemm(int layer,int chunk){
    int l=blockIdx.z;
    int w=2*l+1;
    const float *Are,*Aim,*Bre,*Bim; float *Cre,*Cim;
    int Mst,Nst,Me,Ne,kbeg,kend;
    size_t pa,pb,pc;
    if(layer==0){
        Are=g_Are;Aim=g_Aim;Bre=g_Bre;Bim=g_Bim;
        if(chunk==0){ Cre=g_Cre; Cim=g_Cim; kbeg=0; kend=515; }
        else        { Cre=(float*)g_x1; Cim=((float*)g_x1)+C1SZ; kbeg=515; kend=K1D; }
        Mst=M1H;Nst=N1;Me=BATCH*(l+1);Ne=F1C*w;
        pa=(size_t)l*K1D*M1H; pb=(size_t)l*K1D*N1; pc=(size_t)l*M1H*N1;
    } else {
        Are=g_A2re;Aim=g_A2im;Bre=g_B2re;Bim=g_B2im;Cre=g_C2re;Cim=g_C2im;
        Mst=M2H;Nst=N2;Me=BATCH*(l+1);Ne=F2C*w;kbeg=0;kend=F1C*w;
        pa=(size_t)l*K2D*M2H; pb=(size_t)l*K2D*N2; pc=(size_t)l*M2H*N2;
    }
    int m0=blockIdx.x*64, n0=blockIdx.y*64;
    if(m0>=Me||n0>=Ne) return;
    const float* are=Are+pa;
    const float* aim=Aim+pa;
    const float* bre=Bre+pb;
    const float* bim=Bim+pb;
    float* cre=Cre+pc;
    float* cim=Cim+pc;
    __shared__ __align__(16) float sAr[8][64],sAi[8][64],sBr[8][64],sBi[8][64];
    int tid=threadIdx.x; // 256
    int tx=tid&15, ty=tid>>4;
    float cr[4][4]={}, ci[4][4]={};
    for(int k0=kbeg;k0<kend;k0+=8){
        #pragma unroll
        for(int it=0;it<2;it++){
            int idx=tid+it*256;
            int kk=idx>>6, col=idx&63;
            int krow=k0+kk;
            float ar=0.f,ai=0.f,br=0.f,bi=0.f;
            if(krow<kend){
                int mc=m0+col;
                if(mc<Me){ ar=are[(size_t)krow*Mst+mc]; ai=aim[(size_t)krow*Mst+mc]; }
                int nc=n0+col;
                if(nc<Ne){ br=bre[(size_t)krow*Nst+nc]; bi=bim[(size_t)krow*Nst+nc]; }
            }
            sAr[kk][col]=ar; sAi[kk][col]=ai;
            sBr[kk][col]=br; sBi[kk][col]=bi;
        }
        __syncthreads();
        #pragma unroll
        for(int kk=0;kk<8;kk++){
            float4 arv=*reinterpret_cast<const float4*>(&sAr[kk][ty*4]);
            float4 aiv=*reinterpret_cast<const float4*>(&sAi[kk][ty*4]);
            float4 brv=*reinterpret_cast<const float4*>(&sBr[kk][tx*4]);
            float4 biv=*reinterpret_cast<const float4*>(&sBi[kk][tx*4]);
            float ar[4]={arv.x,arv.y,arv.z,arv.w};
            float ai[4]={aiv.x,aiv.y,aiv.z,aiv.w};
            float br[4]={brv.x,brv.y,brv.z,brv.w};
            float bi[4]={biv.x,biv.y,biv.z,biv.w};
            #pragma unroll
            for(int i=0;i<4;i++)
                #pragma unroll
                for(int j=0;j<4;j++){
                    cr[i][j]=fmaf(ar[i],br[j],cr[i][j]);
                    cr[i][j]=fmaf(-ai[i],bi[j],cr[i][j]);
                    ci[i][j]=fmaf(ar[i],bi[j],ci[i][j]);
                    ci[i][j]=fmaf(ai[i],br[j],ci[i][j]);
                }
        }
        __syncthreads();
    }
    #pragma unroll
    for(int i=0;i<4;i++){
        int m=m0+ty*4+i;
        if(m>=Me) continue;
        #pragma unroll
        for(int j=0;j<4;j++){
            int n=n0+tx*4+j;
            if(n<Ne){
                cre[(size_t)m*Nst+n]=cr[i][j];
                cim[(size_t)m*Nst+n]=ci[i][j];
            }
        }
    }
}

// reduce partial C (chunk 1, stored in g_x1) into g_Cre/g_Cim
__global__ void k_red(){
    int i=blockIdx.x*blockDim.x+threadIdx.x;
    const float* p=(const float*)g_x1;
    if(i<C1SZ) g_Cre[i]+=p[i];
    else if(i<2*C1SZ) g_Cim[i-C1SZ]+=p[i];
}

// SO3 synthesis b1: reconstruct m<0 via C[-m,-n]=(-1)^{m+n}conj(C[m,n])
__global__ void k_syn1(const float* __restrict__ bias1){
    int g=blockIdx.x, b=blockIdx.y;
    int tid=threadIdx.x; // 256
    __shared__ float2 sz[NL1*NM1*NM1];
    __shared__ float2 ssk[NM1*NM1];
    __shared__ float2 st[NA1*NM1];
    for(int i=tid;i<NL1*NM1*NM1;i+=blockDim.x) sz[i]=make_float2(0.f,0.f);
    __syncthreads();
    for(int i=tid;i<1330;i+=blockDim.x){
        int l=0;
        while(c_S10[l+1]<=i) l++;
        int r=i-c_S10[l], w=2*l+1;
        int mi=r/w, ni=r%w;
        int mv=mi-l;
        float2 v;
        if(mv>=0){
            size_t off=(size_t)l*M1H*N1+((size_t)b*(l+1)+mv)*N1+g*w+ni;
            v=make_float2(g_Cre[off],g_Cim[off]);
        } else {
            size_t off=(size_t)l*M1H*N1+((size_t)b*(l+1)+(-mv))*N1+g*w+(w-1-ni);
            float s=((mi+ni)&1)?-1.f:1.f;
            v=make_float2(s*g_Cre[off],-s*g_Cim[off]);
        }
        int m=mi-l+(NL1-1), n=ni-l+(NL1-1);
        sz[l*(NM1*NM1)+m*NM1+n]=v;
    }
    __syncthreads();
    float bv=bias1[g];
    for(int k=0;k<NA1;k++){
        for(int i=tid;i<NM1*NM1;i+=blockDim.x){
            float re=0.f, im=0.f;
            #pragma unroll
            for(int l=0;l<NL1;l++){
                float w=g_d4s1[(k*NL1+l)*(NM1*NM1)+i];
                float2 z=sz[l*(NM1*NM1)+i];
                re=fmaf(w,z.x,re);
                im=fmaf(w,z.y,im);
            }
            ssk[i]=make_float2(re,im);
        }
        __syncthreads();
        for(int i=tid;i<NA1*NM1;i+=blockDim.x){
            int a=i/NM1, n=i%NM1;
            float re=0.f, im=0.f;
            #pragma unroll
            for(int m=0;m<NM1;m++){
                float2 e=g_Es1[m*NA1+a];
                float2 s=ssk[m*NM1+n];
                re+=s.x*e.x-s.y*e.y;
                im+=s.x*e.y+s.y*e.x;
            }
            st[i]=make_float2(re,im);
        }
        __syncthreads();
        for(int i=tid;i<NA1*NA1;i+=blockDim.x){
            int a=i/NA1, c=i%NA1;
            float v=0.f;
            #pragma unroll
            for(int n=0;n<NM1;n++){
                float2 e=g_Es1[n*NA1+c];
                float2 t=st[a*NM1+n];
                v+=t.x*e.x-t.y*e.y;
            }
            v+=bv;
            v=v>0.f?v:0.f;
            g_x1[(((size_t)(b*F1C+g)*NA1+k)*NA1+a)*NA1+c]=v;
        }
        __syncthreads();
    }
}

// SO3 analysis b1 -> half-M packed A2
__global__ void k_t2(){
    int f=blockIdx.x, b=blockIdx.y;
    int tid=threadIdx.x; // 128
    __shared__ float  sx1[NA1*NA1];
    __shared__ float2 stt[NA1*NM2];
    __shared__ float2 su[NM2*NM2];
    __shared__ float2 sacc[NL2*NM2*NM2];
    for(int i=tid;i<NL2*NM2*NM2;i+=blockDim.x) sacc[i]=make_float2(0.f,0.f);
    __syncthreads();
    for(int k=0;k<NA1;k++){
        size_t xb=(((size_t)(b*F1C+f)*NA1+k))*NA1*NA1;
        for(int i=tid;i<NA1*NA1;i+=blockDim.x) sx1[i]=g_x1[xb+i];
        __syncthreads();
        for(int i=tid;i<NA1*NM2;i+=blockDim.x){
            int a=i/NM2, n=i%NM2;
            float re=0.f, im=0.f;
            #pragma unroll
            for(int c=0;c<NA1;c++){
                float xv=sx1[a*NA1+c];
                float2 e=g_Ea2[c*NM2+n];
                re=fmaf(xv,e.x,re);
                im=fmaf(xv,e.y,im);
            }
            stt[i]=make_float2(re,im);
        }
        __syncthreads();
        for(int i=tid;i<NM2*NM2;i+=blockDim.x){
            int m=i/NM2, n=i%NM2;
            float re=0.f, im=0.f;
            #pragma unroll
            for(int a=0;a<NA1;a++){
                float2 e=g_Ea2[a*NM2+m];
                float2 t=stt[a*NM2+n];
                re+=t.x*e.x-t.y*e.y;
                im+=t.x*e.y+t.y*e.x;
            }
            su[i]=make_float2(re,im);
        }
        __syncthreads();
        for(int i=tid;i<NL2*NM2*NM2;i+=blockDim.x){
            int l=i/(NM2*NM2), r=i%(NM2*NM2);
            float w=g_d4a2[(k*NL2+l)*(NM2*NM2)+r];
            float2 u=su[r];
            sacc[i].x=fmaf(w,u.x,sacc[i].x);
            sacc[i].y=fmaf(w,u.y,sacc[i].y);
        }
        __syncthreads();
    }
    for(int i=tid;i<161;i+=blockDim.x){
        int l=0;
        while(c_H6[l+1]<=i) l++;
        int r=i-c_H6[l], w=2*l+1;
        int mv=r/w, pl=r%w;
        int m=mv+(NL2-1), p=pl-l+(NL2-1);
        float2 v=sacc[l*(NM2*NM2)+m*NM2+p];
        size_t off=((size_t)l*K2D+f*w+pl)*M2H+b*(l+1)+mv;
        g_A2re[off]=v.x;
        g_A2im[off]=v.y;
    }
}

// conj(yh2) -> packed B2
__global__ void k_yh2(const float* __restrict__ kern2){
    int g=blockIdx.x, f=blockIdx.y;
    int tid=threadIdx.x; // 128
    __shared__ float skn[NK2];
    size_t kb=((size_t)f*F2C+g)*NK2;
    for(int i=tid;i<NK2;i+=blockDim.x) skn[i]=kern2[kb+i];
    __syncthreads();
    for(int i=tid;i<286;i+=blockDim.x){
        int l=0;
        while(c_S6[l+1]<=i) l++;
        int r=i-c_S6[l], w=2*l+1;
        int nl=r/w, pl=r%w;
        int n=nl-l+(NL2-1), p=pl-l+(NL2-1);
        float re=0.f, im=0.f;
        #pragma unroll 8
        for(int j=0;j<NK2;j++){
            float wk=skn[j];
            float2 kv=g_K2[(j*NL2+l)*(NM2*NM2)+n*NM2+p];
            re=fmaf(wk,kv.x,re);
            im=fmaf(wk,kv.y,im);
        }
        size_t off=((size_t)l*K2D+f*w+pl)*N2+g*w+nl;
        g_B2re[off]=re;
        g_B2im[off]=-im;
    }
}

// SO3 synthesis b2 + bias + relu + quadrature -> feat
__global__ void k_syn2(const float* __restrict__ bias2){
    int g=blockIdx.x, b=blockIdx.y;
    int tid=threadIdx.x; // 128
    __shared__ float2 sz[NL2*NM2*NM2];
    __shared__ float2 ss[NM2*NM2];
    __shared__ float2 st2[NA2*NM2];
    __shared__ float  sred[128];
    for(int i=tid;i<NL2*NM2*NM2;i+=blockDim.x) sz[i]=make_float2(0.f,0.f);
    __syncthreads();
    for(int i=tid;i<286;i+=blockDim.x){
        int l=0;
        while(c_S6[l+1]<=i) l++;
        int r=i-c_S6[l], w=2*l+1;
        int mi=r/w, ni=r%w;
        int mv=mi-l;
        float2 v;
        if(mv>=0){
            size_t off=(size_t)l*M2H*N2+((size_t)b*(l+1)+mv)*N2+g*w+ni;
            v=make_float2(g_C2re[off],g_C2im[off]);
        } else {
            size_t off=(size_t)l*M2H*N2+((size_t)b*(l+1)+(-mv))*N2+g*w+(w-1-ni);
            float s=((mi+ni)&1)?-1.f:1.f;
            v=make_float2(s*g_C2re[off],-s*g_C2im[off]);
        }
        int m=mi-l+(NL2-1), n=ni-l+(NL2-1);
        sz[l*(NM2*NM2)+m*NM2+n]=v;
    }
    __syncthreads();
    float bv=bias2[g];
    float acc=0.f;
    for(int k=0;k<NA2;k++){
        for(int i=tid;i<NM2*NM2;i+=blockDim.x){
            float re=0.f, im=0.f;
            #pragma unroll
            for(int l=0;l<NL2;l++){
                float w=g_d4s2[(k*NL2+l)*(NM2*NM2)+i];
                float2 z=sz[l*(NM2*NM2)+i];
                re=fmaf(w,z.x,re);
                im=fmaf(w,z.y,im);
            }
            ss[i]=make_float2(re,im);
        }
        __syncthreads();
        for(int i=tid;i<NA2*NM2;i+=blockDim.x){
            int a=i/NM2, n=i%NM2;
            float re=0.f, im=0.f;
            #pragma unroll
            for(int m=0;m<NM2;m++){
                float2 e=g_Es2[m*NA2+a];
                float2 s=ss[m*NM2+n];
                re+=s.x*e.x-s.y*e.y;
                im+=s.x*e.y+s.y*e.x;
            }
            st2[i]=make_float2(re,im);
        }
        __syncthreads();
        float wk=g_wint[k];
        for(int i=tid;i<NA2*NA2;i+=blockDim.x){
            int a=i/NA2, c=i%NA2;
            float v=0.f;
            #pragma unroll
            for(int n=0;n<NM2;n++){
                float2 e=g_Es2[n*NA2+c];
                float2 t=st2[a*NM2+n];
                v+=t.x*e.x-t.y*e.y;
            }
            v+=bv;
            v=v>0.f?v:0.f;
            acc+=wk*v;
        }
        __syncthreads();
    }
    sred[tid]=acc;
    __syncthreads();
    for(int s=64;s>0;s>>=1){
        if(tid<s) sred[tid]+=sred[tid+s];
        __syncthreads();
    }
    if(tid==0) g_feat[b*F2C+g]=sred[0];
}

__global__ void k_head(const float* __restrict__ W, const float* __restrict__ b_lin,
                       float* __restrict__ out){
    int idx=threadIdx.x;
    if(idx>=BATCH*2) return;
    int b=idx>>1, i=idx&1;
    float s=b_lin[i];
    #pragma unroll 8
    for(int g=0;g<F2C;g++) s+=g_feat[b*F2C+g]*W[i*F2C+g];
    out[idx]=s;
}

extern "C" void kernel_launch(void* const* d_in, const int* in_sizes, int n_in,
                              void* d_out, int out_size){
    const float* x     = (const float*)d_in[0];
    const float* kern1 = (const float*)d_in[1];
    const float* bias1 = (const float*)d_in[2];
    const float* kern2 = (const float*)d_in[3];
    const float* bias2 = (const float*)d_in[4];
    const float* W     = (const float*)d_in[5];
    const float* b_lin = (const float*)d_in[6];
    float* out = (float*)d_out;
    const int T=128;
    k_rng<<<1,256>>>();
    k_bas1<<<(NBIN*NL1*NM1+NBIN*NM1+T-1)/T,T>>>();
    k_bas_K1<<<(NGRID*NL1*NM1+T-1)/T,T>>>();
    k_xh<<<(BATCH*FIN)/XH_PAIRS,256>>>(x);
    k_yh1<<<dim3(FIN,NL1),256>>>(kern1);
    k_cgemm<<<dim3(10,6,NL1),256>>>(0,0);
    k_cgemm<<<dim3(10,6,NL1),256>>>(0,1);
    k_red<<<(2*C1SZ+255)/256,256>>>();
    k_basA<<<(NA1*NL1*NM1*NM1+NM1*NA1+T-1)/T,T>>>();
    k_basB<<<(NA1*NL2*NM2*NM2+NA1*NM2+NK2*NL2*NM2*NM2+NA2*NL2*NM2*NM2+NM2*NA2+NA2+T-1)/T,T>>>();
    k_syn1<<<dim3(F1C,BATCH),256>>>(bias1);
    k_t2<<<dim3(F1C,BATCH),128>>>();
    k_yh2<<<dim3(F2C,F1C),128>>>(kern2);
    k_cgemm<<<dim3(6,7,NL2),256>>>(1,0);
    k_syn2<<<dim3(F2C,BATCH),128>>>(bias2);
    k_head<<<1,128>>>(W,b_lin,out);
}

// round 17
// speedup vs baseline: 2.4614x; 1.0212x over previous
#include <cuda_runtime.h>
#include <math.h>

#define PI 3.14159265358979323846

#define NBIN 30
#define NM1 19
#define NL1 10
#define NA1 20
#define NM2 11
#define NL2 6
#define NA2 12
#define FIN 1029
#define F1C 20
#define F2C 40
#define BATCH 64
#define NGRID 128
#define NK2 144

#define N1 (F1C*NM1)     // 380
#define K1D FIN          // 1029
#define N2 (F2C*NM2)     // 440
#define K2D (F1C*NM2)    // 220
#define M1H (BATCH*NL1)  // 640
#define M2H (BATCH*NL2)  // 384
#define C1SZ (NL1*M1H*N1)

// scratch
__device__ float g_Are[NL1*K1D*M1H];
__device__ float g_Aim[NL1*K1D*M1H];
__device__ float g_Bre[NL1*K1D*N1];
__device__ float g_Bim[NL1*K1D*N1];
__device__ float g_Cre[C1SZ];
__device__ float g_Cim[C1SZ];
__device__ float g_x1[BATCH*F1C*NA1*NA1*NA1];
__device__ float g_A2re[NL2*K2D*M2H];
__device__ float g_A2im[NL2*K2D*M2H];
__device__ float g_B2re[NL2*K2D*N2];
__device__ float g_B2im[NL2*K2D*N2];
__device__ float g_C2re[NL2*M2H*N2];
__device__ float g_C2im[NL2*M2H*N2];
__device__ float g_feat[BATCH*F2C];

// basis
__device__ float  g_d0w[NBIN*NL1*NM1];
__device__ float2 g_EaIN[NBIN*NM1];
__device__ float2 g_K1[NGRID*NL1*NM1];
__device__ float  g_d4s1[NA1*NL1*NM1*NM1];
__device__ float2 g_Es1[NM1*NA1];
__device__ float  g_d4a2[NA1*NL2*NM2*NM2];
__device__ float2 g_Ea2[NA1*NM2];
__device__ float2 g_K2[NK2*NL2*NM2*NM2];
__device__ float  g_d4s2[NA2*NL2*NM2*NM2];
__device__ float2 g_Es2[NM2*NA2];
__device__ float  g_wint[NA2];
__device__ double g_bg[NGRID];
__device__ double g_ag[NGRID];

__device__ __constant__ int c_S10[11] = {0,1,10,35,84,165,286,455,680,969,1330};
__device__ __constant__ int c_S6[7]   = {0,1,10,35,84,165,286};
__device__ __constant__ int c_T10[11] = {0,1,3,6,10,15,21,28,36,45,55};
__device__ __constant__ int c_H6[7]   = {0,1,7,22,50,95,161};

__device__ __forceinline__ int imax(int a,int b){return a>b?a:b;}
__device__ __forceinline__ int imin(int a,int b){return a<b?a:b;}

// packed f32x2 fma: {a.x*b.x+c.x, a.y*b.y+c.y}
__device__ __forceinline__ float2 ffma2(float2 a, float2 b, float2 c){
    float2 d;
    asm("fma.rn.f32x2 %0, %1, %2, %3;"
        : "=l"(reinterpret_cast<unsigned long long&>(d))
        : "l"(reinterpret_cast<unsigned long long&>(a)),
          "l"(reinterpret_cast<unsigned long long&>(b)),
          "l"(reinterpret_cast<unsigned long long&>(c)));
    return d;
}
__device__ __forceinline__ float2 bc2(float v){ return make_float2(v,v); }

__device__ __forceinline__ double dfact(int n){
    const double f[19] = {1.,1.,2.,6.,24.,120.,720.,5040.,40320.,362880.,3628800.,
        39916800.,479001600.,6227020800.,87178291200.,1307674368000.,
        20922789888000.,355687428096000.,6402373705728000.};
    return f[n];
}

__device__ double wigd(int l,int mp,int mm,double beta){
    double cb=cos(0.5*beta), sb=sin(0.5*beta);
    double pref=sqrt(dfact(l+mp)*dfact(l-mp)*dfact(l+mm)*dfact(l-mm));
    int s0=imax(0,mm-mp), s1=imin(l+mm,l-mp);
    double v=0.0;
    for(int s=s0;s<=s1;s++){
        double term=(((mp-mm+s)&1)?-1.0:1.0)
            /(dfact(l+mm-s)*dfact(s)*dfact(mp-mm+s)*dfact(l-mp-s));
        int ec=2*l+mm-mp-2*s, es=mp-mm+2*s;
        double cp=1.0; for(int t=0;t<ec;t++) cp*=cb;
        double sp=1.0; for(int t=0;t<es;t++) sp*=sb;
        v+=term*cp*sp;
    }
    return pref*v;
}

__device__ double dhw(int b,int k){
    double beta=PI*(2*k+1)/(4.0*b);
    double s=0.0;
    for(int j=0;j<b;j++) s+=sin(beta*(2*j+1))/(double)(2*j+1);
    return (2.0/b)*sin(beta)*s;
}

// ---- 128-bit helpers for PCG64 jump-ahead ----
struct U128{ unsigned long long hi,lo; };
__device__ __forceinline__ U128 u128mul(U128 a,U128 b){
    U128 r;
    r.lo=a.lo*b.lo;
    r.hi=__umul64hi(a.lo,b.lo)+a.lo*b.hi+a.hi*b.lo;
    return r;
}
__device__ __forceinline__ U128 u128add(U128 a,U128 b){
    U128 r;
    r.lo=a.lo+b.lo;
    r.hi=a.hi+b.hi+(r.lo<a.lo?1ull:0ull);
    return r;
}

// numpy default_rng(42): SeedSequence -> PCG64, parallel via LCG jump-ahead.
__global__ void k_rng(){
    int tid=threadIdx.x;            // 256 threads = 256 draws
    unsigned int pool[4];
    unsigned int hc=0x43b0d7e5u;
    auto hashmix=[&hc](unsigned int v){ v^=hc; hc*=0x931e8875u; v*=hc; v^=v>>16; return v; };
    pool[0]=hashmix(42u);
    for(int i=1;i<4;i++) pool[i]=hashmix(0u);
    for(int s=0;s<4;s++)
        for(int d=0;d<4;d++)
            if(s!=d){
                unsigned int h=hashmix(pool[s]);
                unsigned int r=pool[d]*0xca01f9ddu - h*0x4973f715u;
                r^=r>>16;
                pool[d]=r;
            }
    unsigned int hb=0x8b51f9ddu;
    unsigned int st32[8];
    for(int i=0;i<8;i++){
        unsigned int v=pool[i&3];
        v^=hb; hb*=0x58f38dedu; v*=hb; v^=v>>16;
        st32[i]=v;
    }
    unsigned long long w[4];
    for(int i=0;i<4;i++)
        w[i]=(unsigned long long)st32[2*i] | ((unsigned long long)st32[2*i+1]<<32);
    U128 S  ={w[0],w[1]};
    U128 INC={(w[2]<<1)|(w[3]>>63),(w[3]<<1)|1ull};
    U128 M  ={0x2360ed051fc65da4ull,0x4385df649fccf645ull};
    U128 st={0ull,0ull};
    st=u128add(u128mul(st,M),INC);
    st=u128add(st,S);
    st=u128add(u128mul(st,M),INC);
    U128 am={0ull,1ull}, ap={0ull,0ull}, cm=M, cp=INC;
    unsigned int d=(unsigned int)(tid+1);
    U128 one={0ull,1ull};
    while(d){
        if(d&1u){
            ap=u128add(u128mul(ap,cm),cp);
            am=u128mul(am,cm);
        }
        cp=u128mul(u128add(cm,one),cp);
        cm=u128mul(cm,cm);
        d>>=1;
    }
    st=u128add(u128mul(st,am),ap);
    unsigned long long xo=st.hi^st.lo;
    unsigned int rot=(unsigned int)(st.hi>>58);
    unsigned long long r64=(xo>>rot)|(xo<<((64u-rot)&63u));
    double u=(double)(r64>>11)*(1.0/9007199254740992.0);
    if(tid<NGRID) g_bg[tid]=acos(-1.0+2.0*u);
    else if(tid<2*NGRID) g_ag[tid-NGRID]=2.0*PI*u;
}

__global__ void k_bas1(){
    int idx=blockIdx.x*blockDim.x+threadIdx.x;
    if(idx<NBIN*NL1*NM1){
        int k=idx/(NL1*NM1), l=(idx/NM1)%NL1, m=idx%NM1;
        int mv=m-(NL1-1);
        float v=0.f;
        if(mv>=-l&&mv<=l){
            double beta=PI*(2*k+1)/60.0;
            v=(float)(wigd(l,mv,0,beta)*dhw(15,k)/(4.0*PI));
        }
        g_d0w[idx]=v;
        return;
    }
    idx-=NBIN*NL1*NM1;
    if(idx<NBIN*NM1){
        int a=idx/NM1, m=idx%NM1;
        double th=(2.0*PI*a/NBIN)*(double)(m-(NL1-1));
        double sc=2.0*PI/NBIN;
        g_EaIN[idx]=make_float2((float)(cos(th)*sc),(float)(-sin(th)*sc));
    }
}
__global__ void k_bas_K1(){
    int idx=blockIdx.x*blockDim.x+threadIdx.x;
    if(idx>=NGRID*NL1*NM1) return;
    int j=idx/(NL1*NM1), l=(idx/NM1)%NL1, m=idx%NM1;
    int mv=m-(NL1-1);
    float2 v=make_float2(0.f,0.f);
    if(mv>=-l&&mv<=l){
        double d0=wigd(l,mv,0,g_bg[j]);
        double th=g_ag[j]*(double)mv;
        v=make_float2((float)(d0*cos(th)),(float)(-d0*sin(th)));
    }
    g_K1[idx]=v;
}
__global__ void k_basA(){
    int idx=blockIdx.x*blockDim.x+threadIdx.x;
    if(idx<NA1*NL1*NM1*NM1){
        int k=idx/(NL1*NM1*NM1), l=(idx/(NM1*NM1))%NL1;
        int m=(idx/NM1)%NM1, n=idx%NM1;
        int mv=m-(NL1-1), nv=n-(NL1-1);
        float v=0.f;
        if(mv>=-l&&mv<=l&&nv>=-l&&nv<=l){
            double beta=PI*(2*k+1)/40.0;
            v=(float)(wigd(l,mv,nv,beta)*(double)(2*l+1));
        }
        g_d4s1[idx]=v;
        return;
    }
    idx-=NA1*NL1*NM1*NM1;
    if(idx<NM1*NA1){
        int m=idx/NA1, a=idx%NA1;
        double th=(double)(m-(NL1-1))*(2.0*PI*a/NA1);
        g_Es1[idx]=make_float2((float)cos(th),(float)sin(th));
    }
}
__global__ void k_basB(){
    int idx=blockIdx.x*blockDim.x+threadIdx.x;
    if(idx<NA1*NL2*NM2*NM2){
        int k=idx/(NL2*NM2*NM2), l=(idx/(NM2*NM2))%NL2;
        int m=(idx/NM2)%NM2, n=idx%NM2;
        int mv=m-(NL2-1), nv=n-(NL2-1);
        float v=0.f;
        if(mv>=-l&&mv<=l&&nv>=-l&&nv<=l){
            double beta=PI*(2*k+1)/40.0;
            v=(float)(wigd(l,mv,nv,beta)*dhw(10,k)/(8.0*PI*PI));
        }
        g_d4a2[idx]=v;
        return;
    }
    idx-=NA1*NL2*NM2*NM2;
    if(idx<NA1*NM2){
        int a=idx/NM2, m=idx%NM2;
        double th=(2.0*PI*a/NA1)*(double)(m-(NL2-1));
        double sc=2.0*PI/NA1;
        g_Ea2[idx]=make_float2((float)(cos(th)*sc),(float)(-sin(th)*sc));
        return;
    }
    idx-=NA1*NM2;
    if(idx<NK2*NL2*NM2*NM2){
        int j=idx/(NL2*NM2*NM2), l=(idx/(NM2*NM2))%NL2;
        int m=(idx/NM2)%NM2, n=idx%NM2;
        int mv=m-(NL2-1), nv=n-(NL2-1);
        float2 v=make_float2(0.f,0.f);
        if(mv>=-l&&mv<=l&&nv>=-l&&nv<=l){
            int ib=j/48, ia=(j/6)%8, ig=j%6;
            double beta=(double)(ib+1)*(PI/8.0)/3.0;
            double alpha=2.0*PI*ia/8.0;
            double gamma=2.0*PI*ig/6.0;
            double dd=wigd(l,mv,nv,beta);
            double th=alpha*(double)mv+gamma*(double)nv;
            v=make_float2((float)(dd*cos(th)),(float)(-dd*sin(th)));
        }
        g_K2[idx]=v;
        return;
    }
    idx-=NK2*NL2*NM2*NM2;
    if(idx<NA2*NL2*NM2*NM2){
        int k=idx/(NL2*NM2*NM2), l=(idx/(NM2*NM2))%NL2;
        int m=(idx/NM2)%NM2, n=idx%NM2;
        int mv=m-(NL2-1), nv=n-(NL2-1);
        float v=0.f;
        if(mv>=-l&&mv<=l&&nv>=-l&&nv<=l){
            double beta=PI*(2*k+1)/24.0;
            v=(float)(wigd(l,mv,nv,beta)*(double)(2*l+1));
        }
        g_d4s2[idx]=v;
        return;
    }
    idx-=NA2*NL2*NM2*NM2;
    if(idx<NM2*NA2){
        int m=idx/NA2, a=idx%NA2;
        double th=(double)(m-(NL2-1))*(2.0*PI*a/NA2);
        g_Es2[idx]=make_float2((float)cos(th),(float)sin(th));
        return;
    }
    idx-=NM2*NA2;
    if(idx<NA2){
        double sc=(2.0*PI/NA2)*(2.0*PI/NA2)/(8.0*PI*PI);
        g_wint[idx]=(float)(dhw(6,idx)*sc);
    }
}

// S2 analysis: half-M packed A[l][f][ b*(l+1)+mv ], mv >= 0 only. f32x2 FMA.
#define XH_PAIRS 8
__global__ void k_xh(const float* __restrict__ x){
    __shared__ float sbuf[XH_PAIRS*900];
    __shared__ float2 sEa[NBIN*10];
    __shared__ float  sd0[NBIN*55];
    int tid=threadIdx.x;                    // 256
    int r0=blockIdx.x*XH_PAIRS;
    size_t xbase=(size_t)r0*900;
    for(int i=tid;i<XH_PAIRS*900;i+=256) sbuf[i]=x[xbase+i];
    for(int i=tid;i<NBIN*10;i+=256){
        int a=i/10, mv=i%10;
        sEa[i]=g_EaIN[a*NM1+mv+(NL1-1)];
    }
    for(int i=tid;i<NBIN*55;i+=256){
        int k=i/55, hm=i%55;
        int l=0;
        while(c_T10[l+1]<=hm) l++;
        int mv=hm-c_T10[l];
        sd0[i]=g_d0w[(k*NL1+l)*NM1 + mv+(NL1-1)];
    }
    __syncthreads();
    float2 acc1[10];
    int p=tid/NBIN, k=tid%NBIN;
    if(tid<XH_PAIRS*NBIN){
        #pragma unroll
        for(int mv=0;mv<10;mv++) acc1[mv]=make_float2(0.f,0.f);
        #pragma unroll 6
        for(int a=0;a<NBIN;a++){
            float2 xp=bc2(sbuf[p*900+k*NBIN+a]);
            #pragma unroll
            for(int mv=0;mv<10;mv++)
                acc1[mv]=ffma2(xp,sEa[a*10+mv],acc1[mv]);
        }
    }
    __syncthreads();
    if(tid<XH_PAIRS*NBIN){
        #pragma unroll
        for(int mv=0;mv<10;mv++)
            *reinterpret_cast<float2*>(&sbuf[p*600+(k*10+mv)*2])=acc1[mv];
    }
    __syncthreads();
    for(int o=tid;o<XH_PAIRS*55;o+=256){
        int pp=o/55, hm=o%55;
        int l=0;
        while(c_T10[l+1]<=hm) l++;
        int mv=hm-c_T10[l];
        float2 acc=make_float2(0.f,0.f);
        #pragma unroll 6
        for(int kk=0;kk<NBIN;kk++){
            float2 e=*reinterpret_cast<const float2*>(&sbuf[pp*600+(kk*10+mv)*2]);
            acc=ffma2(bc2(sd0[kk*55+hm]),e,acc);
        }
        int r=r0+pp;
        int b=r/FIN, f=r%FIN;
        size_t off=((size_t)l*FIN+f)*M1H + b*(l+1)+mv;
        g_Are[off]=acc.x;
        g_Aim[off]=acc.y;
    }
}

// conj(yh) full-width B (n-symmetry halves the reduction). f32x2 FMA.
__global__ void k_yh1(const float* __restrict__ kern1){
    int f=blockIdx.x, l=blockIdx.y;
    int w=2*l+1;
    int tid=threadIdx.x; // 256
    __shared__ float  sk1[F1C*NGRID];
    __shared__ float2 sK1[NGRID*NM1];
    size_t kb=(size_t)f*F1C*NGRID;
    for(int i=tid;i<F1C*NGRID;i+=blockDim.x) sk1[i]=kern1[kb+i];
    for(int i=tid;i<NGRID*NM1;i+=blockDim.x){
        int j=i/NM1, n=i%NM1;
        float2 v=g_K1[(j*NL1+l)*NM1+n];
        sK1[i]=make_float2(v.x,-v.y);
    }
    __syncthreads();
    int tot=F1C*(l+1);
    for(int o=tid;o<tot;o+=blockDim.x){
        int g=o/(l+1), mv=o%(l+1);
        int n=mv+(NL1-1);
        float2 acc=make_float2(0.f,0.f);
        #pragma unroll 8
        for(int j=0;j<NGRID;j++)
            acc=ffma2(bc2(sk1[g*NGRID+j]),sK1[j*NM1+n],acc);
        size_t ob=((size_t)l*FIN+f)*N1+g*w;
        g_Bre[ob+l+mv]=acc.x;
        g_Bim[ob+l+mv]=acc.y;
        if(mv>0){
            float s=(mv&1)?-1.f:1.f;
            g_Bre[ob+l-mv]=s*acc.x;
            g_Bim[ob+l-mv]=-s*acc.y;
        }
    }
}

// complex TN GEMM, packed (cr,ci) accumulators via f32x2 FMA
__global__ void k_cgemm(int layer,int chunk){
    int l=blockIdx.z;
    int w=2*l+1;
    const float *Are,*Aim,*Bre,*Bim; float *Cre,*Cim;
    int Mst,Nst,Me,Ne,kbeg,kend;
    size_t pa,pb,pc;
    if(layer==0){
        Are=g_Are;Aim=g_Aim;Bre=g_Bre;Bim=g_Bim;
        if(chunk==0){ Cre=g_Cre; Cim=g_Cim; kbeg=0; kend=515; }
        else        { Cre=(float*)g_x1; Cim=((float*)g_x1)+C1SZ; kbeg=515; kend=K1D; }
        Mst=M1H;Nst=N1;Me=BATCH*(l+1);Ne=F1C*w;
        pa=(size_t)l*K1D*M1H; pb=(size_t)l*K1D*N1; pc=(size_t)l*M1H*N1;
    } else {
        Are=g_A2re;Aim=g_A2im;Bre=g_B2re;Bim=g_B2im;Cre=g_C2re;Cim=g_C2im;
        Mst=M2H;Nst=N2;Me=BATCH*(l+1);Ne=F2C*w;kbeg=0;kend=F1C*w;
        pa=(size_t)l*K2D*M2H; pb=(size_t)l*K2D*N2; pc=(size_t)l*M2H*N2;
    }
    int m0=blockIdx.x*64, n0=blockIdx.y*64;
    if(m0>=Me||n0>=Ne) return;
    const float* are=Are+pa;
    const float* aim=Aim+pa;
    const float* bre=Bre+pb;
    const float* bim=Bim+pb;
    float* cre=Cre+pc;
    float* cim=Cim+pc;
    __shared__ __align__(16) float sAr[8][64],sAi[8][64],sBr[8][64],sBi[8][64];
    int tid=threadIdx.x; // 256
    int tx=tid&15, ty=tid>>4;
    float2 acc[4][4];
    #pragma unroll
    for(int i=0;i<4;i++)
        #pragma unroll
        for(int j=0;j<4;j++) acc[i][j]=make_float2(0.f,0.f);
    for(int k0=kbeg;k0<kend;k0+=8){
        #pragma unroll
        for(int it=0;it<2;it++){
            int idx=tid+it*256;
            int kk=idx>>6, col=idx&63;
            int krow=k0+kk;
            float ar=0.f,ai=0.f,br=0.f,bi=0.f;
            if(krow<kend){
                int mc=m0+col;
                if(mc<Me){ ar=are[(size_t)krow*Mst+mc]; ai=aim[(size_t)krow*Mst+mc]; }
                int nc=n0+col;
                if(nc<Ne){ br=bre[(size_t)krow*Nst+nc]; bi=bim[(size_t)krow*Nst+nc]; }
            }
            sAr[kk][col]=ar; sAi[kk][col]=ai;
            sBr[kk][col]=br; sBi[kk][col]=bi;
        }
        __syncthreads();
        #pragma unroll
        for(int kk=0;kk<8;kk++){
            float4 arv=*reinterpret_cast<const float4*>(&sAr[kk][ty*4]);
            float4 aiv=*reinterpret_cast<const float4*>(&sAi[kk][ty*4]);
            float4 brv=*reinterpret_cast<const float4*>(&sBr[kk][tx*4]);
            float4 biv=*reinterpret_cast<const float4*>(&sBi[kk][tx*4]);
            float ar[4]={arv.x,arv.y,arv.z,arv.w};
            float ai[4]={aiv.x,aiv.y,aiv.z,aiv.w};
            float br[4]={brv.x,brv.y,brv.z,brv.w};
            float bi[4]={biv.x,biv.y,biv.z,biv.w};
            float2 bp[4],bn[4];
            #pragma unroll
            for(int j=0;j<4;j++){
                bp[j]=make_float2(br[j],bi[j]);
                bn[j]=make_float2(-bi[j],br[j]);
            }
            #pragma unroll
            for(int i=0;i<4;i++){
                float2 a1=bc2(ar[i]);
                float2 a2=bc2(ai[i]);
                #pragma unroll
                for(int j=0;j<4;j++){
                    acc[i][j]=ffma2(a1,bp[j],acc[i][j]);
                    acc[i][j]=ffma2(a2,bn[j],acc[i][j]);
                }
            }
        }
        __syncthreads();
    }
    #pragma unroll
    for(int i=0;i<4;i++){
        int m=m0+ty*4+i;
        if(m>=Me) continue;
        #pragma unroll
        for(int j=0;j<4;j++){
            int n=n0+tx*4+j;
            if(n<Ne){
                cre[(size_t)m*Nst+n]=acc[i][j].x;
                cim[(size_t)m*Nst+n]=acc[i][j].y;
            }
        }
    }
}

// reduce partial C (chunk 1, stored in g_x1) into g_Cre/g_Cim
__global__ void k_red(){
    int i=blockIdx.x*blockDim.x+threadIdx.x;
    const float* p=(const float*)g_x1;
    if(i<C1SZ) g_Cre[i]+=p[i];
    else if(i<2*C1SZ) g_Cim[i-C1SZ]+=p[i];
}

// SO3 synthesis b1: reconstruct m<0 via C[-m,-n]=(-1)^{m+n}conj(C[m,n]). f32x2 FMA.
__global__ void k_syn1(const float* __restrict__ bias1){
    int g=blockIdx.x, b=blockIdx.y;
    int tid=threadIdx.x; // 256
    __shared__ float2 sz[NL1*NM1*NM1];
    __shared__ float2 ssk[NM1*NM1];
    __shared__ float2 st[NA1*NM1];
    for(int i=tid;i<NL1*NM1*NM1;i+=blockDim.x) sz[i]=make_float2(0.f,0.f);
    __syncthreads();
    for(int i=tid;i<1330;i+=blockDim.x){
        int l=0;
        while(c_S10[l+1]<=i) l++;
        int r=i-c_S10[l], w=2*l+1;
        int mi=r/w, ni=r%w;
        int mv=mi-l;
        float2 v;
        if(mv>=0){
            size_t off=(size_t)l*M1H*N1+((size_t)b*(l+1)+mv)*N1+g*w+ni;
            v=make_float2(g_Cre[off],g_Cim[off]);
        } else {
            size_t off=(size_t)l*M1H*N1+((size_t)b*(l+1)+(-mv))*N1+g*w+(w-1-ni);
            float s=((mi+ni)&1)?-1.f:1.f;
            v=make_float2(s*g_Cre[off],-s*g_Cim[off]);
        }
        int m=mi-l+(NL1-1), n=ni-l+(NL1-1);
        sz[l*(NM1*NM1)+m*NM1+n]=v;
    }
    __syncthreads();
    float bv=bias1[g];
    for(int k=0;k<NA1;k++){
        for(int i=tid;i<NM1*NM1;i+=blockDim.x){
            float2 acc=make_float2(0.f,0.f);
            #pragma unroll
            for(int l=0;l<NL1;l++)
                acc=ffma2(bc2(g_d4s1[(k*NL1+l)*(NM1*NM1)+i]),sz[l*(NM1*NM1)+i],acc);
            ssk[i]=acc;
        }
        __syncthreads();
        for(int i=tid;i<NA1*NM1;i+=blockDim.x){
            int a=i/NM1, n=i%NM1;
            float2 acc=make_float2(0.f,0.f);
            #pragma unroll
            for(int m=0;m<NM1;m++){
                float2 e=g_Es1[m*NA1+a];
                float2 s=ssk[m*NM1+n];
                acc=ffma2(bc2(s.x),e,acc);
                acc=ffma2(bc2(s.y),make_float2(-e.y,e.x),acc);
            }
            st[i]=acc;
        }
        __syncthreads();
        for(int i=tid;i<NA1*NA1;i+=blockDim.x){
            int a=i/NA1, c=i%NA1;
            float v=0.f;
            #pragma unroll
            for(int n=0;n<NM1;n++){
                float2 e=g_Es1[n*NA1+c];
                float2 t=st[a*NM1+n];
                v+=t.x*e.x-t.y*e.y;
            }
            v+=bv;
            v=v>0.f?v:0.f;
            g_x1[(((size_t)(b*F1C+g)*NA1+k)*NA1+a)*NA1+c]=v;
        }
        __syncthreads();
    }
}

// SO3 analysis b1 -> half-M packed A2. f32x2 FMA.
__global__ void k_t2(){
    int f=blockIdx.x, b=blockIdx.y;
    int tid=threadIdx.x; // 128
    __shared__ float  sx1[NA1*NA1];
    __shared__ float2 stt[NA1*NM2];
    __shared__ float2 su[NM2*NM2];
    __shared__ float2 sacc[NL2*NM2*NM2];
    for(int i=tid;i<NL2*NM2*NM2;i+=blockDim.x) sacc[i]=make_float2(0.f,0.f);
    __syncthreads();
    for(int k=0;k<NA1;k++){
        size_t xb=(((size_t)(b*F1C+f)*NA1+k))*NA1*NA1;
        for(int i=tid;i<NA1*NA1;i+=blockDim.x) sx1[i]=g_x1[xb+i];
        __syncthreads();
        for(int i=tid;i<NA1*NM2;i+=blockDim.x){
            int a=i/NM2, n=i%NM2;
            float2 acc=make_float2(0.f,0.f);
            #pragma unroll
            for(int c=0;c<NA1;c++)
                acc=ffma2(bc2(sx1[a*NA1+c]),g_Ea2[c*NM2+n],acc);
            stt[i]=acc;
        }
        __syncthreads();
        for(int i=tid;i<NM2*NM2;i+=blockDim.x){
            int m=i/NM2, n=i%NM2;
            float2 acc=make_float2(0.f,0.f);
            #pragma unroll
            for(int a=0;a<NA1;a++){
                float2 e=g_Ea2[a*NM2+m];
                float2 t=stt[a*NM2+n];
                acc=ffma2(bc2(t.x),e,acc);
                acc=ffma2(bc2(t.y),make_float2(-e.y,e.x),acc);
            }
            su[i]=acc;
        }
        __syncthreads();
        for(int i=tid;i<NL2*NM2*NM2;i+=blockDim.x){
            int l=i/(NM2*NM2), r=i%(NM2*NM2);
            sacc[i]=ffma2(bc2(g_d4a2[(k*NL2+l)*(NM2*NM2)+r]),su[r],sacc[i]);
        }
        __syncthreads();
    }
    for(int i=tid;i<161;i+=blockDim.x){
        int l=0;
        while(c_H6[l+1]<=i) l++;
        int r=i-c_H6[l], w=2*l+1;
        int mv=r/w, pl=r%w;
        int m=mv+(NL2-1), p=pl-l+(NL2-1);
        float2 v=sacc[l*(NM2*NM2)+m*NM2+p];
        size_t off=((size_t)l*K2D+f*w+pl)*M2H+b*(l+1)+mv;
        g_A2re[off]=v.x;
        g_A2im[off]=v.y;
    }
}

// conj(yh2) -> packed B2. f32x2 FMA.
__global__ void k_yh2(const float* __restrict__ kern2){
    int g=blockIdx.x, f=blockIdx.y;
    int tid=threadIdx.x; // 128
    __shared__ float skn[NK2];
    size_t kb=((size_t)f*F2C+g)*NK2;
    for(int i=tid;i<NK2;i+=blockDim.x) skn[i]=kern2[kb+i];
    __syncthreads();
    for(int i=tid;i<286;i+=blockDim.x){
        int l=0;
        while(c_S6[l+1]<=i) l++;
        int r=i-c_S6[l], w=2*l+1;
        int nl=r/w, pl=r%w;
        int n=nl-l+(NL2-1), p=pl-l+(NL2-1);
        float2 acc=make_float2(0.f,0.f);
        #pragma unroll 8
        for(int j=0;j<NK2;j++)
            acc=ffma2(bc2(skn[j]),g_K2[(j*NL2+l)*(NM2*NM2)+n*NM2+p],acc);
        size_t off=((size_t)l*K2D+f*w+pl)*N2+g*w+nl;
        g_B2re[off]=acc.x;
        g_B2im[off]=-acc.y;
    }
}

// SO3 synthesis b2 + bias + relu + quadrature -> feat. f32x2 FMA.
__global__ void k_syn2(const float* __restrict__ bias2){
    int g=blockIdx.x, b=blockIdx.y;
    int tid=threadIdx.x; // 128
    __shared__ float2 sz[NL2*NM2*NM2];
    __shared__ float2 ss[NM2*NM2];
    __shared__ float2 st2[NA2*NM2];
    __shared__ float  sred[128];
    for(int i=tid;i<NL2*NM2*NM2;i+=blockDim.x) sz[i]=make_float2(0.f,0.f);
    __syncthreads();
    for(int i=tid;i<286;i+=blockDim.x){
        int l=0;
        while(c_S6[l+1]<=i) l++;
        int r=i-c_S6[l], w=2*l+1;
        int mi=r/w, ni=r%w;
        int mv=mi-l;
        float2 v;
        if(mv>=0){
            size_t off=(size_t)l*M2H*N2+((size_t)b*(l+1)+mv)*N2+g*w+ni;
            v=make_float2(g_C2re[off],g_C2im[off]);
        } else {
            size_t off=(size_t)l*M2H*N2+((size_t)b*(l+1)+(-mv))*N2+g*w+(w-1-ni);
            float s=((mi+ni)&1)?-1.f:1.f;
            v=make_float2(s*g_C2re[off],-s*g_C2im[off]);
        }
        int m=mi-l+(NL2-1), n=ni-l+(NL2-1);
        sz[l*(NM2*NM2)+m*NM2+n]=v;
    }
    __syncthreads();
    float bv=bias2[g];
    float acc=0.f;
    for(int k=0;k<NA2;k++){
        for(int i=tid;i<NM2*NM2;i+=blockDim.x){
            float2 a2=make_float2(0.f,0.f);
            #pragma unroll
            for(int l=0;l<NL2;l++)
                a2=ffma2(bc2(g_d4s2[(k*NL2+l)*(NM2*NM2)+i]),sz[l*(NM2*NM2)+i],a2);
            ss[i]=a2;
        }
        __syncthreads();
        for(int i=tid;i<NA2*NM2;i+=blockDim.x){
            int a=i/NM2, n=i%NM2;
            float2 a2=make_float2(0.f,0.f);
            #pragma unroll
            for(int m=0;m<NM2;m++){
                float2 e=g_Es2[m*NA2+a];
                float2 s=ss[m*NM2+n];
                a2=ffma2(bc2(s.x),e,a2);
                a2=ffma2(bc2(s.y),make_float2(-e.y,e.x),a2);
            }
            st2[i]=a2;
        }
        __syncthreads();
        float wk=g_wint[k];
        for(int i=tid;i<NA2*NA2;i+=blockDim.x){
            int a=i/NA2, c=i%NA2;
            float v=0.f;
            #pragma unroll
            for(int n=0;n<NM2;n++){
                float2 e=g_Es2[n*NA2+c];
                float2 t=st2[a*NM2+n];
                v+=t.x*e.x-t.y*e.y;
            }
            v+=bv;
            v=v>0.f?v:0.f;
            acc+=wk*v;
        }
        __syncthreads();
    }
    sred[tid]=acc;
    __syncthreads();
    for(int s=64;s>0;s>>=1){
        if(tid<s) sred[tid]+=sred[tid+s];
        __syncthreads();
    }
    if(tid==0) g_feat[b*F2C+g]=sred[0];
}

__global__ void k_head(const float* __restrict__ W, const float* __restrict__ b_lin,
                       float* __restrict__ out){
    int idx=threadIdx.x;
    if(idx>=BATCH*2) return;
    int b=idx>>1, i=idx&1;
    float s=b_lin[i];
    #pragma unroll 8
    for(int g=0;g<F2C;g++) s+=g_feat[b*F2C+g]*W[i*F2C+g];
    out[idx]=s;
}

extern "C" void kernel_launch(void* const* d_in, const int* in_sizes, int n_in,
                              void* d_out, int out_size){
    const float* x     = (const float*)d_in[0];
    const float* kern1 = (const float*)d_in[1];
    const float* bias1 = (const float*)d_in[2];
    const float* kern2 = (const float*)d_in[3];
    const float* bias2 = (const float*)d_in[4];
    const float* W     = (const float*)d_in[5];
    const float* b_lin = (const float*)d_in[6];
    float* out = (float*)d_out;
    const int T=128;
    k_rng<<<1,256>>>();
    k_bas1<<<(NBIN*NL1*NM1+NBIN*NM1+T-1)/T,T>>>();
    k_bas_K1<<<(NGRID*NL1*NM1+T-1)/T,T>>>();
    k_xh<<<(BATCH*FIN)/XH_PAIRS,256>>>(x);
    k_yh1<<<dim3(FIN,NL1),256>>>(kern1);
    k_cgemm<<<dim3(10,6,NL1),256>>>(0,0);
    k_cgemm<<<dim3(10,6,NL1),256>>>(0,1);
    k_red<<<(2*C1SZ+255)/256,256>>>();
    k_basA<<<(NA1*NL1*NM1*NM1+NM1*NA1+T-1)/T,T>>>();
    k_basB<<<(NA1*NL2*NM2*NM2+NA1*NM2+NK2*NL2*NM2*NM2+NA2*NL2*NM2*NM2+NM2*NA2+NA2+T-1)/T,T>>>();
    k_syn1<<<dim3(F1C,BATCH),256>>>(bias1);
    k_t2<<<dim3(F1C,BATCH),128>>>();
    k_yh2<<<dim3(F2C,F1C),128>>>(kern2);
    k_cgemm<<<dim3(6,7,NL2),256>>>(1,0);
    k_syn2<<<dim3(F2C,BATCH),128>>>(bias2);
    k_head<<<1,128>>>(W,b_lin,out);
}